// round 4
// baseline (speedup 1.0000x reference)
#include <cuda_runtime.h>
#include <cstdint>
#include <cstddef>

// Problem constants (reference: N=50000, E=800000, 128->128->64)
#define MAXN 50000
#define MAXE 800000
#define DIN  128
#define DHID 128
#define DOUT 64

// Scratch (static device globals -- no allocation anywhere)
__device__ float g_h1  [(size_t)MAXN * DHID];   // x @ W1
__device__ float g_agg1[(size_t)MAXN * DHID];   // self-loop + edge aggregation, layer 1
__device__ float g_h2  [(size_t)MAXN * DOUT];   // relu(agg1+b1) @ W2
__device__ float g_agg2[(size_t)MAXN * DOUT];   // self-loop + edge aggregation, layer 2
__device__ float g_dinv[MAXN];
__device__ float g_deg [MAXN];

// ---------------------------------------------------------------------------
// Degree / normalization
// ---------------------------------------------------------------------------
__global__ void k_zero_deg(int n) {
    int i = blockIdx.x * blockDim.x + threadIdx.x;
    if (i < n) g_deg[i] = 0.0f;
}

__global__ void k_count(const int* __restrict__ dst, int ne) {
    int e = blockIdx.x * blockDim.x + threadIdx.x;
    if (e < ne) atomicAdd(&g_deg[__ldg(dst + e)], 1.0f);
}

__global__ void k_dinv(int n) {
    int i = blockIdx.x * blockDim.x + threadIdx.x;
    if (i < n) g_dinv[i] = rsqrtf(g_deg[i] + 1.0f);
}

// ---------------------------------------------------------------------------
// GEMM: C[n, NCOL] = A[n,128] @ B[128, NCOL]
//   LAYER==1: A = x (param),           writes g_h1,  g_agg1 = g_h1  * dinv^2
//   LAYER==2: A = relu(g_agg1 + b1),   writes g_h2,  g_agg2 = g_h2  * dinv^2
// Block: 256 threads, tile BM=64 x BN=NCOL, K chunked by 32.
// Thread micro-tile: 4 rows x (NCOL/16) cols.
// ---------------------------------------------------------------------------
template <int LAYER>
__global__ void __launch_bounds__(256) k_gemm(
    const float* __restrict__ A_in, const float* __restrict__ B,
    const float* __restrict__ biasA, int n)
{
    constexpr int NCOL = (LAYER == 1) ? DHID : DOUT;
    constexpr bool ACT = (LAYER == 2);
    constexpr int TN = NCOL / 16;            // 8 or 4
    const float* A = (LAYER == 1) ? A_in : (const float*)g_agg1;
    float* H   = (LAYER == 1) ? g_h1   : g_h2;
    float* AGG = (LAYER == 1) ? g_agg1 : g_agg2;

    __shared__ float As[64][36];             // pad 36: bank = (4r + k) % 32
    __shared__ float Bs[32][NCOL];

    const int tid  = threadIdx.x;
    const int tx   = tid & 15;               // col group
    const int ty   = tid >> 4;               // row group
    const int row0 = blockIdx.x * 64;

    float acc[4][TN];
#pragma unroll
    for (int i = 0; i < 4; i++)
#pragma unroll
        for (int j = 0; j < TN; j++) acc[i][j] = 0.0f;

#pragma unroll 1
    for (int kc = 0; kc < 4; kc++) {
        // Stage A chunk: 64 rows x 32 cols  (512 float4, 2 per thread)
#pragma unroll
        for (int i = tid; i < 512; i += 256) {
            int r = i >> 3, c4 = i & 7;
            int grow = row0 + r;
            float4 v = make_float4(0.f, 0.f, 0.f, 0.f);
            if (grow < n) {
                v = ((const float4*)(A + (size_t)grow * 128))[kc * 8 + c4];
                if (ACT) {
                    float4 bb = ((const float4*)biasA)[kc * 8 + c4];
                    v.x = fmaxf(v.x + bb.x, 0.f);
                    v.y = fmaxf(v.y + bb.y, 0.f);
                    v.z = fmaxf(v.z + bb.z, 0.f);
                    v.w = fmaxf(v.w + bb.w, 0.f);
                }
            }
            ((float4*)&As[r][0])[c4] = v;    // row pitch 144B, 16B aligned
        }
        // Stage B chunk: 32 x NCOL
        constexpr int NV = 32 * NCOL / 4;
#pragma unroll
        for (int i = tid; i < NV; i += 256) {
            int k = i / (NCOL / 4), c = i % (NCOL / 4);
            ((float4*)&Bs[k][0])[c] =
                ((const float4*)(B + (size_t)(kc * 32 + k) * NCOL))[c];
        }
        __syncthreads();

#pragma unroll
        for (int k = 0; k < 32; k++) {
            float a[4];
#pragma unroll
            for (int i = 0; i < 4; i++) a[i] = As[ty * 4 + i][k];
            float b[TN];
#pragma unroll
            for (int j = 0; j < TN; j += 4) {
                float4 bv = ((float4*)&Bs[k][0])[(tx * TN + j) >> 2];
                b[j] = bv.x; b[j + 1] = bv.y; b[j + 2] = bv.z; b[j + 3] = bv.w;
            }
#pragma unroll
            for (int i = 0; i < 4; i++)
#pragma unroll
                for (int j = 0; j < TN; j++)
                    acc[i][j] = fmaf(a[i], b[j], acc[i][j]);
        }
        __syncthreads();
    }

    // Epilogue: write H and AGG = H * dinv^2 (self-loop term; also pre-inits AGG
    // so the scatter kernel needs no zeroing pass).
#pragma unroll
    for (int i = 0; i < 4; i++) {
        int grow = row0 + ty * 4 + i;
        if (grow < n) {
            float dv = g_dinv[grow];
            float sn = dv * dv;
#pragma unroll
            for (int j = 0; j < TN; j += 4) {
                float4 v = make_float4(acc[i][j], acc[i][j + 1],
                                       acc[i][j + 2], acc[i][j + 3]);
                ((float4*)(H + (size_t)grow * NCOL))[(tx * TN + j) >> 2] = v;
                float4 w = make_float4(v.x * sn, v.y * sn, v.z * sn, v.w * sn);
                ((float4*)(AGG + (size_t)grow * NCOL))[(tx * TN + j) >> 2] = w;
            }
        }
    }
}

// ---------------------------------------------------------------------------
// Edge scatter: one warp per edge, vectorized L2 reductions (red.global.add.vN).
// Lane 0 loads the edge endpoints + norms, broadcasts via shfl (cuts redundant
// index/dinv loads 32x).
// ---------------------------------------------------------------------------
__global__ void __launch_bounds__(256) k_scatter1(
    const int* __restrict__ src, const int* __restrict__ dst, int ne)
{
    int w = (blockIdx.x * 256 + threadIdx.x) >> 5;
    int lane = threadIdx.x & 31;
    if (w >= ne) return;
    int s = 0, d = 0;
    float nrm = 0.f;
    if (lane == 0) {
        s = __ldg(src + w);
        d = __ldg(dst + w);
        nrm = __ldg(g_dinv + s) * __ldg(g_dinv + d);
    }
    s   = __shfl_sync(0xffffffffu, s, 0);
    d   = __shfl_sync(0xffffffffu, d, 0);
    nrm = __shfl_sync(0xffffffffu, nrm, 0);

    float4 h = ((const float4*)(g_h1 + (size_t)s * DHID))[lane];
    float4* p = ((float4*)(g_agg1 + (size_t)d * DHID)) + lane;
    asm volatile("red.global.add.v4.f32 [%0], {%1, %2, %3, %4};"
                 :: "l"(p), "f"(h.x * nrm), "f"(h.y * nrm),
                    "f"(h.z * nrm), "f"(h.w * nrm)
                 : "memory");
}

__global__ void __launch_bounds__(256) k_scatter2(
    const int* __restrict__ src, const int* __restrict__ dst, int ne)
{
    int w = (blockIdx.x * 256 + threadIdx.x) >> 5;
    int lane = threadIdx.x & 31;
    if (w >= ne) return;
    int s = 0, d = 0;
    float nrm = 0.f;
    if (lane == 0) {
        s = __ldg(src + w);
        d = __ldg(dst + w);
        nrm = __ldg(g_dinv + s) * __ldg(g_dinv + d);
    }
    s   = __shfl_sync(0xffffffffu, s, 0);
    d   = __shfl_sync(0xffffffffu, d, 0);
    nrm = __shfl_sync(0xffffffffu, nrm, 0);

    float2 h = ((const float2*)(g_h2 + (size_t)s * DOUT))[lane];
    float2* p = ((float2*)(g_agg2 + (size_t)d * DOUT)) + lane;
    asm volatile("red.global.add.v2.f32 [%0], {%1, %2};"
                 :: "l"(p), "f"(h.x * nrm), "f"(h.y * nrm)
                 : "memory");
}

// ---------------------------------------------------------------------------
// Final: out = relu(agg2 + b2)
// ---------------------------------------------------------------------------
__global__ void __launch_bounds__(256) k_final2(
    const float* __restrict__ b2, float* __restrict__ out, int n)
{
    int t = blockIdx.x * 256 + threadIdx.x;      // over n*16 float4
    if (t < n * (DOUT / 4)) {
        int c4 = t & (DOUT / 4 - 1);
        float4 v = ((const float4*)g_agg2)[t];
        float4 bb = ((const float4*)b2)[c4];
        v.x = fmaxf(v.x + bb.x, 0.f);
        v.y = fmaxf(v.y + bb.y, 0.f);
        v.z = fmaxf(v.z + bb.z, 0.f);
        v.w = fmaxf(v.w + bb.w, 0.f);
        ((float4*)out)[t] = v;
    }
}

// ---------------------------------------------------------------------------
extern "C" void kernel_launch(void* const* d_in, const int* in_sizes, int n_in,
                              void* d_out, int out_size)
{
    const float* x  = (const float*)d_in[0];
    const int*   ei = (const int*)  d_in[1];
    const float* W1 = (const float*)d_in[2];
    const float* b1 = (const float*)d_in[3];
    const float* W2 = (const float*)d_in[4];
    const float* b2 = (const float*)d_in[5];
    float* out = (float*)d_out;

    const int n  = in_sizes[0] / DIN;    // 50000
    const int ne = in_sizes[1] / 2;      // 800000
    const int* src = ei;
    const int* dst = ei + ne;

    const int nb_n  = (n + 255) / 256;
    const int nb_e  = (ne + 255) / 256;
    const int nb_g  = (n + 63) / 64;
    const int nb_s  = (ne + 7) / 8;      // warp per edge, 8 edges/block
    const int nb_f  = (n * (DOUT / 4) + 255) / 256;

    k_zero_deg<<<nb_n, 256>>>(n);
    k_count<<<nb_e, 256>>>(dst, ne);
    k_dinv<<<nb_n, 256>>>(n);

    k_gemm<1><<<nb_g, 256>>>(x, W1, nullptr, n);     // h1, agg1 init
    k_scatter1<<<nb_s, 256>>>(src, dst, ne);         // agg1 += edges

    k_gemm<2><<<nb_g, 256>>>(nullptr, W2, b1, n);    // A = relu(agg1+b1); h2, agg2 init
    k_scatter2<<<nb_s, 256>>>(src, dst, ne);         // agg2 += edges

    k_final2<<<nb_f, 256>>>(b2, out, n);
}

// round 5
// speedup vs baseline: 1.0994x; 1.0994x over previous
#include <cuda_runtime.h>
#include <cstdint>
#include <cstddef>

// Problem constants (reference: N=50000, E=800000, 128->128->64)
#define MAXN 50000
#define MAXE 800000
#define DIN  128
#define DHID 128
#define DOUT 64

// Scratch (static device globals -- no allocation anywhere)
__device__ float g_h1  [(size_t)MAXN * DHID];   // x @ W1
__device__ float g_agg1[(size_t)MAXN * DHID];   // self-loop + edge aggregation, layer 1
__device__ float g_h2  [(size_t)MAXN * DOUT];   // relu(agg1+b1) @ W2
__device__ float g_agg2[(size_t)MAXN * DOUT];   // self-loop + edge aggregation, layer 2
__device__ float g_dinv[MAXN];
__device__ float g_deg [MAXN];

// ---------------------------------------------------------------------------
// Degree / normalization
// ---------------------------------------------------------------------------
__global__ void k_zero_deg(int n) {
    int i = blockIdx.x * blockDim.x + threadIdx.x;
    if (i < n) g_deg[i] = 0.0f;
}

__global__ void k_count(const int* __restrict__ dst, int ne) {
    int e = blockIdx.x * blockDim.x + threadIdx.x;
    if (e < ne) atomicAdd(&g_deg[__ldg(dst + e)], 1.0f);
}

__global__ void k_dinv(int n) {
    int i = blockIdx.x * blockDim.x + threadIdx.x;
    if (i < n) g_dinv[i] = rsqrtf(g_deg[i] + 1.0f);
}

// ---------------------------------------------------------------------------
// GEMM: C[n, NCOL] = A[n,128] @ B[128, NCOL]
//   LAYER==1: A = x (param),           writes g_h1,  g_agg1 = g_h1  * dinv^2
//   LAYER==2: A = relu(g_agg1 + b1),   writes g_h2,  g_agg2 = g_h2  * dinv^2
// Block: 256 threads = 16 col-groups (tx) x 16 row-groups (ty).
// Tile BM=128 rows x NCOL cols; thread micro-tile: 8 rows x TN cols.
// Per k-step: 8 A-LDS.32 (broadcast) + 2 B-LDS.128 for 8*TN FMAs.
// ---------------------------------------------------------------------------
template <int LAYER>
__global__ void __launch_bounds__(256, 2) k_gemm(
    const float* __restrict__ A_in, const float* __restrict__ B,
    const float* __restrict__ biasA, int n)
{
    constexpr int NCOL = (LAYER == 1) ? DHID : DOUT;
    constexpr bool ACT = (LAYER == 2);
    constexpr int TN = NCOL / 16;            // 8 or 4
    constexpr int BM = 128;
    const float* A = (LAYER == 1) ? A_in : (const float*)g_agg1;
    float* H   = (LAYER == 1) ? g_h1   : g_h2;
    float* AGG = (LAYER == 1) ? g_agg1 : g_agg2;

    __shared__ float As[BM][36];             // [row][k-chunk 32], pad->36
    __shared__ float Bs[32][NCOL];

    const int tid  = threadIdx.x;
    const int tx   = tid & 15;               // col group
    const int ty   = tid >> 4;               // row group (8 rows each)
    const int row0 = blockIdx.x * BM;

    float acc[8][TN];
#pragma unroll
    for (int i = 0; i < 8; i++)
#pragma unroll
        for (int j = 0; j < TN; j++) acc[i][j] = 0.0f;

#pragma unroll 1
    for (int kc = 0; kc < 4; kc++) {
        // Stage A chunk: 128 rows x 32 k  (1024 float4, 4 per thread)
#pragma unroll
        for (int i = tid; i < BM * 8; i += 256) {
            int r = i >> 3, c4 = i & 7;
            int grow = row0 + r;
            float4 v = make_float4(0.f, 0.f, 0.f, 0.f);
            if (grow < n) {
                v = ((const float4*)(A + (size_t)grow * 128))[kc * 8 + c4];
                if (ACT) {
                    float4 bb = ((const float4*)biasA)[kc * 8 + c4];
                    v.x = fmaxf(v.x + bb.x, 0.f);
                    v.y = fmaxf(v.y + bb.y, 0.f);
                    v.z = fmaxf(v.z + bb.z, 0.f);
                    v.w = fmaxf(v.w + bb.w, 0.f);
                }
            }
            ((float4*)&As[r][0])[c4] = v;    // row pitch 144B, 16B aligned
        }
        // Stage B chunk: 32 x NCOL
        constexpr int NV = 32 * NCOL / 4;
#pragma unroll
        for (int i = tid; i < NV; i += 256) {
            int k = i / (NCOL / 4), c = i % (NCOL / 4);
            ((float4*)&Bs[k][0])[c] =
                ((const float4*)(B + (size_t)(kc * 32 + k) * NCOL))[c];
        }
        __syncthreads();

#pragma unroll
        for (int k = 0; k < 32; k++) {
            float a[8];
#pragma unroll
            for (int i = 0; i < 8; i++) a[i] = As[ty * 8 + i][k];
            float b[TN];
#pragma unroll
            for (int j = 0; j < TN; j += 4) {
                float4 bv = ((float4*)&Bs[k][0])[(tx * TN + j) >> 2];
                b[j] = bv.x; b[j + 1] = bv.y; b[j + 2] = bv.z; b[j + 3] = bv.w;
            }
#pragma unroll
            for (int i = 0; i < 8; i++)
#pragma unroll
                for (int j = 0; j < TN; j++)
                    acc[i][j] = fmaf(a[i], b[j], acc[i][j]);
        }
        __syncthreads();
    }

    // Epilogue: write H and AGG = H * dinv^2 (self-loop term; also pre-inits AGG
    // so the scatter kernel needs no zeroing pass).
#pragma unroll
    for (int i = 0; i < 8; i++) {
        int grow = row0 + ty * 8 + i;
        if (grow < n) {
            float dv = g_dinv[grow];
            float sn = dv * dv;
#pragma unroll
            for (int j = 0; j < TN; j += 4) {
                float4 v = make_float4(acc[i][j], acc[i][j + 1],
                                       acc[i][j + 2], acc[i][j + 3]);
                ((float4*)(H + (size_t)grow * NCOL))[(tx * TN + j) >> 2] = v;
                float4 w = make_float4(v.x * sn, v.y * sn, v.z * sn, v.w * sn);
                ((float4*)(AGG + (size_t)grow * NCOL))[(tx * TN + j) >> 2] = w;
            }
        }
    }
}

// ---------------------------------------------------------------------------
// Edge scatter: one warp per edge, vectorized L2 reductions (red.global.add.vN).
// Lane 0 loads the edge endpoints + norms, broadcasts via shfl.
// ---------------------------------------------------------------------------
__global__ void __launch_bounds__(256) k_scatter1(
    const int* __restrict__ src, const int* __restrict__ dst, int ne)
{
    int w = (blockIdx.x * 256 + threadIdx.x) >> 5;
    int lane = threadIdx.x & 31;
    if (w >= ne) return;
    int s = 0, d = 0;
    float nrm = 0.f;
    if (lane == 0) {
        s = __ldg(src + w);
        d = __ldg(dst + w);
        nrm = __ldg(g_dinv + s) * __ldg(g_dinv + d);
    }
    s   = __shfl_sync(0xffffffffu, s, 0);
    d   = __shfl_sync(0xffffffffu, d, 0);
    nrm = __shfl_sync(0xffffffffu, nrm, 0);

    float4 h = ((const float4*)(g_h1 + (size_t)s * DHID))[lane];
    float4* p = ((float4*)(g_agg1 + (size_t)d * DHID)) + lane;
    asm volatile("red.global.add.v4.f32 [%0], {%1, %2, %3, %4};"
                 :: "l"(p), "f"(h.x * nrm), "f"(h.y * nrm),
                    "f"(h.z * nrm), "f"(h.w * nrm)
                 : "memory");
}

__global__ void __launch_bounds__(256) k_scatter2(
    const int* __restrict__ src, const int* __restrict__ dst, int ne)
{
    int w = (blockIdx.x * 256 + threadIdx.x) >> 5;
    int lane = threadIdx.x & 31;
    if (w >= ne) return;
    int s = 0, d = 0;
    float nrm = 0.f;
    if (lane == 0) {
        s = __ldg(src + w);
        d = __ldg(dst + w);
        nrm = __ldg(g_dinv + s) * __ldg(g_dinv + d);
    }
    s   = __shfl_sync(0xffffffffu, s, 0);
    d   = __shfl_sync(0xffffffffu, d, 0);
    nrm = __shfl_sync(0xffffffffu, nrm, 0);

    float2 h = ((const float2*)(g_h2 + (size_t)s * DOUT))[lane];
    float2* p = ((float2*)(g_agg2 + (size_t)d * DOUT)) + lane;
    asm volatile("red.global.add.v2.f32 [%0], {%1, %2};"
                 :: "l"(p), "f"(h.x * nrm), "f"(h.y * nrm)
                 : "memory");
}

// ---------------------------------------------------------------------------
// Final: out = relu(agg2 + b2)
// ---------------------------------------------------------------------------
__global__ void __launch_bounds__(256) k_final2(
    const float* __restrict__ b2, float* __restrict__ out, int n)
{
    int t = blockIdx.x * 256 + threadIdx.x;      // over n*16 float4
    if (t < n * (DOUT / 4)) {
        int c4 = t & (DOUT / 4 - 1);
        float4 v = ((const float4*)g_agg2)[t];
        float4 bb = ((const float4*)b2)[c4];
        v.x = fmaxf(v.x + bb.x, 0.f);
        v.y = fmaxf(v.y + bb.y, 0.f);
        v.z = fmaxf(v.z + bb.z, 0.f);
        v.w = fmaxf(v.w + bb.w, 0.f);
        ((float4*)out)[t] = v;
    }
}

// ---------------------------------------------------------------------------
extern "C" void kernel_launch(void* const* d_in, const int* in_sizes, int n_in,
                              void* d_out, int out_size)
{
    const float* x  = (const float*)d_in[0];
    const int*   ei = (const int*)  d_in[1];
    const float* W1 = (const float*)d_in[2];
    const float* b1 = (const float*)d_in[3];
    const float* W2 = (const float*)d_in[4];
    const float* b2 = (const float*)d_in[5];
    float* out = (float*)d_out;

    const int n  = in_sizes[0] / DIN;    // 50000
    const int ne = in_sizes[1] / 2;      // 800000
    const int* src = ei;
    const int* dst = ei + ne;

    const int nb_n  = (n + 255) / 256;
    const int nb_e  = (ne + 255) / 256;
    const int nb_g  = (n + 127) / 128;
    const int nb_s  = (ne + 7) / 8;      // warp per edge, 8 edges/block
    const int nb_f  = (n * (DOUT / 4) + 255) / 256;

    k_zero_deg<<<nb_n, 256>>>(n);
    k_count<<<nb_e, 256>>>(dst, ne);
    k_dinv<<<nb_n, 256>>>(n);

    k_gemm<1><<<nb_g, 256>>>(x, W1, nullptr, n);     // h1, agg1 init
    k_scatter1<<<nb_s, 256>>>(src, dst, ne);         // agg1 += edges

    k_gemm<2><<<nb_g, 256>>>(nullptr, W2, b1, n);    // A = relu(agg1+b1); h2, agg2 init
    k_scatter2<<<nb_s, 256>>>(src, dst, ne);         // agg2 += edges

    k_final2<<<nb_f, 256>>>(b2, out, n);
}

// round 8
// speedup vs baseline: 1.9342x; 1.7592x over previous
#include <cuda_runtime.h>
#include <cstdint>
#include <cstddef>

// Problem constants (reference: N=50000, E=800000, 128->128->64)
#define MAXN 50048
#define MAXE 800000
#define DIN  128
#define DHID 128
#define DOUT 64

// Scratch (static device globals -- no allocation anywhere).
// NOTE: these are ONLY referenced from device code (host code cannot take
// the address of a __device__ symbol -- that was the R6 bug).
__device__ float g_ht1 [(size_t)MAXN * DHID];   // (x @ W1) * dinv[row]
__device__ float g_agg1[(size_t)MAXN * DHID];   // layer-1 aggregated output
__device__ float g_ht2 [(size_t)MAXN * DOUT];   // (relu(agg1+b1) @ W2) * dinv[row]
__device__ float g_dinv[MAXN];
__device__ int   g_deg [MAXN];
__device__ int   g_rows[MAXN + 1];              // CSR row starts
__device__ int   g_cur [MAXN];                  // fill cursors
__device__ int   g_bsum[64];                    // scan block sums
__device__ int   g_csr [MAXE];                  // src node per CSR slot

// ---------------------------------------------------------------------------
// Degree / normalization / CSR build
// ---------------------------------------------------------------------------
__global__ void k_zero(int n) {
    int i = blockIdx.x * blockDim.x + threadIdx.x;
    if (i < n) g_deg[i] = 0;
}

__global__ void k_count(const int* __restrict__ dst, int ne) {
    int e = blockIdx.x * blockDim.x + threadIdx.x;
    if (e < ne) atomicAdd(&g_deg[__ldg(dst + e)], 1);
}

__global__ void k_dinv(int n) {
    int i = blockIdx.x * blockDim.x + threadIdx.x;
    if (i < n) g_dinv[i] = rsqrtf((float)g_deg[i] + 1.0f);
}

// Hierarchical exclusive scan of g_deg -> g_rows. Stage 1: per-1024-block.
__global__ void k_scan1(int n) {
    __shared__ int s[1024];
    int tid = threadIdx.x;
    int i = blockIdx.x * 1024 + tid;
    int v = (i < n) ? g_deg[i] : 0;
    s[tid] = v;
    __syncthreads();
    for (int o = 1; o < 1024; o <<= 1) {
        int t = (tid >= o) ? s[tid - o] : 0;
        __syncthreads();
        s[tid] += t;
        __syncthreads();
    }
    if (i < n) g_rows[i] = s[tid] - v;           // exclusive within block
    if (tid == 1023) g_bsum[blockIdx.x] = s[1023];
}

// Stage 2: scan the (<=64) block sums serially; also set g_rows[n].
__global__ void k_scan2(int nb, int n) {
    if (threadIdx.x == 0) {
        int run = 0;
        for (int b = 0; b < nb; b++) { int t = g_bsum[b]; g_bsum[b] = run; run += t; }
        g_rows[n] = run;                          // == ne
    }
}

// Stage 3: add block offsets; init cursors.
__global__ void k_scan3(int n) {
    int i = blockIdx.x * blockDim.x + threadIdx.x;
    if (i < n) {
        int r = g_rows[i] + g_bsum[i >> 10];
        g_rows[i] = r;
        g_cur[i] = r;
    }
}

__global__ void k_fill(const int* __restrict__ src, const int* __restrict__ dst, int ne) {
    int e = blockIdx.x * blockDim.x + threadIdx.x;
    if (e < ne) {
        int d = __ldg(dst + e);
        int pos = atomicAdd(&g_cur[d], 1);
        g_csr[pos] = __ldg(src + e);
    }
}

// ---------------------------------------------------------------------------
// GEMM: HT[n, NCOL] = (A[n,128] @ B[128, NCOL]) * dinv[row]
//   LAYER==1: A = x (param)          -> g_ht1
//   LAYER==2: A = relu(g_agg1 + b1)  -> g_ht2
// Block: 256 threads; tile BM=128 x NCOL; micro-tile 8 rows x TN cols.
// ---------------------------------------------------------------------------
template <int LAYER>
__global__ void __launch_bounds__(256, 2) k_gemm(
    const float* __restrict__ A_in, const float* __restrict__ B,
    const float* __restrict__ biasA, int n)
{
    constexpr int NCOL = (LAYER == 1) ? DHID : DOUT;
    constexpr bool ACT = (LAYER == 2);
    constexpr int TN = NCOL / 16;            // 8 or 4
    constexpr int BM = 128;
    const float* A = (LAYER == 1) ? A_in : (const float*)g_agg1;
    float* HT = (LAYER == 1) ? g_ht1 : g_ht2;

    __shared__ float As[BM][36];             // [row][k-chunk 32], pad->36
    __shared__ float Bs[32][NCOL];

    const int tid  = threadIdx.x;
    const int tx   = tid & 15;               // col group
    const int ty   = tid >> 4;               // row group (8 rows each)
    const int row0 = blockIdx.x * BM;

    float acc[8][TN];
#pragma unroll
    for (int i = 0; i < 8; i++)
#pragma unroll
        for (int j = 0; j < TN; j++) acc[i][j] = 0.0f;

#pragma unroll 1
    for (int kc = 0; kc < 4; kc++) {
        // Stage A chunk: 128 rows x 32 k  (1024 float4, 4 per thread)
#pragma unroll
        for (int i = tid; i < BM * 8; i += 256) {
            int r = i >> 3, c4 = i & 7;
            int grow = row0 + r;
            float4 v = make_float4(0.f, 0.f, 0.f, 0.f);
            if (grow < n) {
                v = ((const float4*)(A + (size_t)grow * 128))[kc * 8 + c4];
                if (ACT) {
                    float4 bb = ((const float4*)biasA)[kc * 8 + c4];
                    v.x = fmaxf(v.x + bb.x, 0.f);
                    v.y = fmaxf(v.y + bb.y, 0.f);
                    v.z = fmaxf(v.z + bb.z, 0.f);
                    v.w = fmaxf(v.w + bb.w, 0.f);
                }
            }
            ((float4*)&As[r][0])[c4] = v;
        }
        // Stage B chunk: 32 x NCOL
        constexpr int NV = 32 * NCOL / 4;
#pragma unroll
        for (int i = tid; i < NV; i += 256) {
            int k = i / (NCOL / 4), c = i % (NCOL / 4);
            ((float4*)&Bs[k][0])[c] =
                ((const float4*)(B + (size_t)(kc * 32 + k) * NCOL))[c];
        }
        __syncthreads();

#pragma unroll
        for (int k = 0; k < 32; k++) {
            float a[8];
#pragma unroll
            for (int i = 0; i < 8; i++) a[i] = As[ty * 8 + i][k];
            float b[TN];
#pragma unroll
            for (int j = 0; j < TN; j += 4) {
                float4 bv = ((float4*)&Bs[k][0])[(tx * TN + j) >> 2];
                b[j] = bv.x; b[j + 1] = bv.y; b[j + 2] = bv.z; b[j + 3] = bv.w;
            }
#pragma unroll
            for (int i = 0; i < 8; i++)
#pragma unroll
                for (int j = 0; j < TN; j++)
                    acc[i][j] = fmaf(a[i], b[j], acc[i][j]);
        }
        __syncthreads();
    }

    // Epilogue: HT = acc * dinv[row]
#pragma unroll
    for (int i = 0; i < 8; i++) {
        int grow = row0 + ty * 8 + i;
        if (grow < n) {
            float dv = g_dinv[grow];
#pragma unroll
            for (int j = 0; j < TN; j += 4) {
                float4 v = make_float4(acc[i][j] * dv, acc[i][j + 1] * dv,
                                       acc[i][j + 2] * dv, acc[i][j + 3] * dv);
                ((float4*)(HT + (size_t)grow * NCOL))[(tx * TN + j) >> 2] = v;
            }
        }
    }
}

// ---------------------------------------------------------------------------
// CSR gather: one warp per node.
//   out[d] = dinv[d] * (ht[d] + sum_{s in N(d)} ht[s])   [+ bias, relu if LAYER==2]
// LAYER==1: HT=g_ht1 (NCOL=128), OUT=g_agg1
// LAYER==2: HT=g_ht2 (NCOL=64),  OUT=out_param (+b2, relu)
// ---------------------------------------------------------------------------
template <int LAYER>
__global__ void __launch_bounds__(256) k_gather(
    float* __restrict__ out_param, const float* __restrict__ bias, int n)
{
    constexpr int NCOL = (LAYER == 1) ? DHID : DOUT;
    const float* HT = (LAYER == 1) ? g_ht1 : g_ht2;
    float* OUT = (LAYER == 1) ? g_agg1 : out_param;

    int w = (blockIdx.x * 256 + threadIdx.x) >> 5;
    int lane = threadIdx.x & 31;
    if (w >= n) return;

    int rs = 0, re = 0;
    float dv = 0.f;
    if (lane == 0) {
        rs = g_rows[w];
        re = g_rows[w + 1];
        dv = g_dinv[w];
    }
    rs = __shfl_sync(0xffffffffu, rs, 0);
    re = __shfl_sync(0xffffffffu, re, 0);
    dv = __shfl_sync(0xffffffffu, dv, 0);

    if (LAYER == 1) {
        float4 a0 = ((const float4*)(HT + (size_t)w * NCOL))[lane];  // self term
        float4 a1 = make_float4(0.f, 0.f, 0.f, 0.f);
        for (int base = rs; base < re; base += 32) {
            int cnt = min(32, re - base);
            int idx = (lane < cnt) ? __ldg(g_csr + base + lane) : 0;
            int k = 0;
            for (; k + 2 <= cnt; k += 2) {
                int s0 = __shfl_sync(0xffffffffu, idx, k);
                int s1 = __shfl_sync(0xffffffffu, idx, k + 1);
                float4 v0 = ((const float4*)(HT + (size_t)s0 * NCOL))[lane];
                float4 v1 = ((const float4*)(HT + (size_t)s1 * NCOL))[lane];
                a0.x += v0.x; a0.y += v0.y; a0.z += v0.z; a0.w += v0.w;
                a1.x += v1.x; a1.y += v1.y; a1.z += v1.z; a1.w += v1.w;
            }
            if (k < cnt) {
                int s0 = __shfl_sync(0xffffffffu, idx, k);
                float4 v0 = ((const float4*)(HT + (size_t)s0 * NCOL))[lane];
                a0.x += v0.x; a0.y += v0.y; a0.z += v0.z; a0.w += v0.w;
            }
        }
        float4 r = make_float4((a0.x + a1.x) * dv, (a0.y + a1.y) * dv,
                               (a0.z + a1.z) * dv, (a0.w + a1.w) * dv);
        ((float4*)(OUT + (size_t)w * NCOL))[lane] = r;
    } else {
        float2 a0 = ((const float2*)(HT + (size_t)w * NCOL))[lane];
        float2 a1 = make_float2(0.f, 0.f);
        for (int base = rs; base < re; base += 32) {
            int cnt = min(32, re - base);
            int idx = (lane < cnt) ? __ldg(g_csr + base + lane) : 0;
            int k = 0;
            for (; k + 2 <= cnt; k += 2) {
                int s0 = __shfl_sync(0xffffffffu, idx, k);
                int s1 = __shfl_sync(0xffffffffu, idx, k + 1);
                float2 v0 = ((const float2*)(HT + (size_t)s0 * NCOL))[lane];
                float2 v1 = ((const float2*)(HT + (size_t)s1 * NCOL))[lane];
                a0.x += v0.x; a0.y += v0.y;
                a1.x += v1.x; a1.y += v1.y;
            }
            if (k < cnt) {
                int s0 = __shfl_sync(0xffffffffu, idx, k);
                float2 v0 = ((const float2*)(HT + (size_t)s0 * NCOL))[lane];
                a0.x += v0.x; a0.y += v0.y;
            }
        }
        float2 r = make_float2((a0.x + a1.x) * dv, (a0.y + a1.y) * dv);
        float2 bb = ((const float2*)bias)[lane];
        r.x = fmaxf(r.x + bb.x, 0.f);
        r.y = fmaxf(r.y + bb.y, 0.f);
        ((float2*)(OUT + (size_t)w * NCOL))[lane] = r;
    }
}

// ---------------------------------------------------------------------------
extern "C" void kernel_launch(void* const* d_in, const int* in_sizes, int n_in,
                              void* d_out, int out_size)
{
    const float* x  = (const float*)d_in[0];
    const int*   ei = (const int*)  d_in[1];
    const float* W1 = (const float*)d_in[2];
    const float* b1 = (const float*)d_in[3];
    const float* W2 = (const float*)d_in[4];
    const float* b2 = (const float*)d_in[5];
    float* out = (float*)d_out;

    const int n  = in_sizes[0] / DIN;    // 50000
    const int ne = in_sizes[1] / 2;      // 800000
    const int* src = ei;
    const int* dst = ei + ne;

    const int nb_n = (n + 255) / 256;
    const int nb_e = (ne + 255) / 256;
    const int nb_g = (n + 127) / 128;
    const int nb_w = (n + 7) / 8;        // warp per node
    const int nb_sc = (n + 1023) / 1024; // scan blocks (<=64)

    // CSR build
    k_zero<<<nb_n, 256>>>(n);
    k_count<<<nb_e, 256>>>(dst, ne);
    k_dinv<<<nb_n, 256>>>(n);
    k_scan1<<<nb_sc, 1024>>>(n);
    k_scan2<<<1, 32>>>(nb_sc, n);
    k_scan3<<<nb_n, 256>>>(n);
    k_fill<<<nb_e, 256>>>(src, dst, ne);

    // Layer 1
    k_gemm<1><<<nb_g, 256>>>(x, W1, nullptr, n);       // g_ht1 = (x@W1)*dinv
    k_gather<1><<<nb_w, 256>>>(nullptr, nullptr, n);   // g_agg1

    // Layer 2 (gather writes final output: +b2, relu)
    k_gemm<2><<<nb_g, 256>>>(nullptr, W2, b1, n);      // g_ht2 = (relu(agg1+b1)@W2)*dinv
    k_gather<2><<<nb_w, 256>>>(out, b2, n);            // out
}

// round 9
// speedup vs baseline: 2.5057x; 1.2955x over previous
#include <cuda_runtime.h>
#include <cstdint>
#include <cstddef>

// Problem constants (reference: N=50000, E=800000, 128->128->64)
#define MAXN 50048
#define MAXE 800000
#define DIN  128
#define DHID 128
#define DOUT 64

// Scratch (static device globals -- no allocation anywhere).
// Only referenced from device code (host can't take __device__ addresses).
__device__ float g_ht1 [(size_t)MAXN * DHID];   // (x @ W1) * dinv[row]
__device__ float g_agg1[(size_t)MAXN * DHID];   // layer-1 aggregated output
__device__ float g_ht2 [(size_t)MAXN * DOUT];   // (relu(agg1+b1) @ W2) * dinv[row]
__device__ float g_dinv[MAXN];
__device__ int   g_deg [MAXN];
__device__ int   g_rows[MAXN + 1];              // CSR row starts
__device__ int   g_cur [MAXN];                  // fill cursors
__device__ int   g_bsum[64];                    // scan block sums
__device__ int   g_csr [MAXE];                  // src node per CSR slot

// ---------------------------------------------------------------------------
// Degree / normalization / CSR build
// ---------------------------------------------------------------------------
__global__ void k_zero(int n) {
    int i = blockIdx.x * blockDim.x + threadIdx.x;
    if (i < n) g_deg[i] = 0;
}

__global__ void k_count(const int* __restrict__ dst, int ne) {
    int e = blockIdx.x * blockDim.x + threadIdx.x;
    if (e < ne) atomicAdd(&g_deg[__ldg(dst + e)], 1);
}

// Stage 1: per-1024-block scan of g_deg; also computes g_dinv (fused).
__global__ void k_scan1(int n) {
    __shared__ int s[1024];
    int tid = threadIdx.x;
    int i = blockIdx.x * 1024 + tid;
    int v = (i < n) ? g_deg[i] : 0;
    if (i < n) g_dinv[i] = rsqrtf((float)v + 1.0f);
    s[tid] = v;
    __syncthreads();
    for (int o = 1; o < 1024; o <<= 1) {
        int t = (tid >= o) ? s[tid - o] : 0;
        __syncthreads();
        s[tid] += t;
        __syncthreads();
    }
    if (i < n) g_rows[i] = s[tid] - v;           // exclusive within block
    if (tid == 1023) g_bsum[blockIdx.x] = s[1023];
}

// Stage 2: scan the (<=64) block sums serially; set g_rows[n].
__global__ void k_scan2(int nb, int n) {
    if (threadIdx.x == 0) {
        int run = 0;
        for (int b = 0; b < nb; b++) { int t = g_bsum[b]; g_bsum[b] = run; run += t; }
        g_rows[n] = run;
    }
}

// Stage 3: add block offsets; init cursors.
__global__ void k_scan3(int n) {
    int i = blockIdx.x * blockDim.x + threadIdx.x;
    if (i < n) {
        int r = g_rows[i] + g_bsum[i >> 10];
        g_rows[i] = r;
        g_cur[i] = r;
    }
}

__global__ void k_fill(const int* __restrict__ src, const int* __restrict__ dst, int ne) {
    int e = blockIdx.x * blockDim.x + threadIdx.x;
    if (e < ne) {
        int d = __ldg(dst + e);
        int pos = atomicAdd(&g_cur[d], 1);
        g_csr[pos] = __ldg(src + e);
    }
}

// ---------------------------------------------------------------------------
// tf32 helpers
// ---------------------------------------------------------------------------
__device__ __forceinline__ uint32_t f2tf32(float f) {
    uint32_t r;
    asm("cvt.rna.tf32.f32 %0, %1;" : "=r"(r) : "f"(f));
    return r;
}

__device__ __forceinline__ void mma_tf32(float c[4],
    uint32_t a0, uint32_t a1, uint32_t a2, uint32_t a3,
    uint32_t b0, uint32_t b1)
{
    asm volatile(
        "mma.sync.aligned.m16n8k8.row.col.f32.tf32.tf32.f32 "
        "{%0,%1,%2,%3}, {%4,%5,%6,%7}, {%8,%9}, {%0,%1,%2,%3};"
        : "+f"(c[0]), "+f"(c[1]), "+f"(c[2]), "+f"(c[3])
        : "r"(a0), "r"(a1), "r"(a2), "r"(a3), "r"(b0), "r"(b1));
}

// ---------------------------------------------------------------------------
// Tensor-core GEMM: HT[n, NCOL] = (A[n,128] @ B[128, NCOL]) * dinv[row]
//   LAYER==1: A = x (param)          -> g_ht1
//   LAYER==2: A = relu(g_agg1 + b1)  -> g_ht2
// 256 threads = 8 warps (2m x 4n). CTA tile 128 x NCOL; warp tile 64 x NCOL/4.
// mma.m16n8k8 tf32; K chunked by 32 (4 chunks).
// ---------------------------------------------------------------------------
template <int LAYER>
__global__ void __launch_bounds__(256, 2) k_gemm(
    const float* __restrict__ A_in, const float* __restrict__ B,
    const float* __restrict__ biasA, int n)
{
    constexpr int NCOL = (LAYER == 1) ? DHID : DOUT;
    constexpr bool ACT = (LAYER == 2);
    constexpr int BM = 128;
    constexpr int WN = NCOL / 4;             // warp n-tile: 32 or 16
    constexpr int MA = 4;                    // m16 atoms per warp (64/16)
    constexpr int NA = WN / 8;               // n8 atoms per warp: 4 or 2
    constexpr int BSTRIDE = NCOL + 8;        // bank-free B fragment loads

    const float* A = (LAYER == 1) ? A_in : (const float*)g_agg1;
    float* HT = (LAYER == 1) ? g_ht1 : g_ht2;

    __shared__ uint32_t As[BM][36];          // tf32 bits; bank = (4r+c)%32
    __shared__ uint32_t Bs[32][BSTRIDE];     // tf32 bits; bank = (8k+c)%32

    const int tid  = threadIdx.x;
    const int wid  = tid >> 5;
    const int lane = tid & 31;
    const int g    = lane >> 2;              // group id (0..7)
    const int tg   = lane & 3;               // thread-in-group (0..3)
    const int warp_m = (wid >> 2) * 64;      // 0 or 64
    const int warp_n = (wid & 3) * WN;
    const int row0 = blockIdx.x * BM;

    float acc[MA][NA][4];
#pragma unroll
    for (int am = 0; am < MA; am++)
#pragma unroll
        for (int an = 0; an < NA; an++)
#pragma unroll
            for (int i = 0; i < 4; i++) acc[am][an][i] = 0.0f;

#pragma unroll 1
    for (int kc = 0; kc < 4; kc++) {
        // Stage A chunk: 128 rows x 32 k (1024 float4, 4 per thread), tf32-convert
#pragma unroll
        for (int i = tid; i < BM * 8; i += 256) {
            int r = i >> 3, c4 = i & 7;
            int grow = row0 + r;
            float4 v = make_float4(0.f, 0.f, 0.f, 0.f);
            if (grow < n) {
                v = ((const float4*)(A + (size_t)grow * 128))[kc * 8 + c4];
                if (ACT) {
                    float4 bb = ((const float4*)biasA)[kc * 8 + c4];
                    v.x = fmaxf(v.x + bb.x, 0.f);
                    v.y = fmaxf(v.y + bb.y, 0.f);
                    v.z = fmaxf(v.z + bb.z, 0.f);
                    v.w = fmaxf(v.w + bb.w, 0.f);
                }
            }
            uint4 t;
            t.x = f2tf32(v.x); t.y = f2tf32(v.y);
            t.z = f2tf32(v.z); t.w = f2tf32(v.w);
            ((uint4*)&As[r][0])[c4] = t;
        }
        // Stage B chunk: 32 x NCOL, tf32-convert
        constexpr int NV = 32 * NCOL / 4;
#pragma unroll
        for (int i = tid; i < NV; i += 256) {
            int k = i / (NCOL / 4), c = i % (NCOL / 4);
            float4 v = ((const float4*)(B + (size_t)(kc * 32 + k) * NCOL))[c];
            uint4 t;
            t.x = f2tf32(v.x); t.y = f2tf32(v.y);
            t.z = f2tf32(v.z); t.w = f2tf32(v.w);
            ((uint4*)&Bs[k][0])[c] = t;
        }
        __syncthreads();

#pragma unroll
        for (int ks = 0; ks < 4; ks++) {
            const int k0 = ks * 8;
            uint32_t af[MA][4];
#pragma unroll
            for (int am = 0; am < MA; am++) {
                int r = warp_m + am * 16 + g;
                af[am][0] = As[r]    [k0 + tg];
                af[am][1] = As[r + 8][k0 + tg];
                af[am][2] = As[r]    [k0 + tg + 4];
                af[am][3] = As[r + 8][k0 + tg + 4];
            }
            uint32_t bf[NA][2];
#pragma unroll
            for (int an = 0; an < NA; an++) {
                int c = warp_n + an * 8 + g;
                bf[an][0] = Bs[k0 + tg]    [c];
                bf[an][1] = Bs[k0 + tg + 4][c];
            }
#pragma unroll
            for (int am = 0; am < MA; am++)
#pragma unroll
                for (int an = 0; an < NA; an++)
                    mma_tf32(acc[am][an], af[am][0], af[am][1], af[am][2],
                             af[am][3], bf[an][0], bf[an][1]);
        }
        __syncthreads();
    }

    // Epilogue: HT = acc * dinv[row]
#pragma unroll
    for (int am = 0; am < MA; am++) {
        int r_lo = row0 + warp_m + am * 16 + g;
        int r_hi = r_lo + 8;
        float dv_lo = (r_lo < n) ? g_dinv[r_lo] : 0.f;
        float dv_hi = (r_hi < n) ? g_dinv[r_hi] : 0.f;
#pragma unroll
        for (int an = 0; an < NA; an++) {
            int col = warp_n + an * 8 + tg * 2;
            if (r_lo < n) {
                float2 v = make_float2(acc[am][an][0] * dv_lo,
                                       acc[am][an][1] * dv_lo);
                *(float2*)(HT + (size_t)r_lo * NCOL + col) = v;
            }
            if (r_hi < n) {
                float2 v = make_float2(acc[am][an][2] * dv_hi,
                                       acc[am][an][3] * dv_hi);
                *(float2*)(HT + (size_t)r_hi * NCOL + col) = v;
            }
        }
    }
}

// ---------------------------------------------------------------------------
// CSR gather: one warp per node.
//   out[d] = dinv[d] * (ht[d] + sum_{s in N(d)} ht[s])   [+ bias, relu if LAYER==2]
// ---------------------------------------------------------------------------
template <int LAYER>
__global__ void __launch_bounds__(256) k_gather(
    float* __restrict__ out_param, const float* __restrict__ bias, int n)
{
    constexpr int NCOL = (LAYER == 1) ? DHID : DOUT;
    const float* HT = (LAYER == 1) ? g_ht1 : g_ht2;
    float* OUT = (LAYER == 1) ? g_agg1 : out_param;

    int w = (blockIdx.x * 256 + threadIdx.x) >> 5;
    int lane = threadIdx.x & 31;
    if (w >= n) return;

    int rs = 0, re = 0;
    float dv = 0.f;
    if (lane == 0) {
        rs = g_rows[w];
        re = g_rows[w + 1];
        dv = g_dinv[w];
    }
    rs = __shfl_sync(0xffffffffu, rs, 0);
    re = __shfl_sync(0xffffffffu, re, 0);
    dv = __shfl_sync(0xffffffffu, dv, 0);

    if (LAYER == 1) {
        float4 a0 = ((const float4*)(HT + (size_t)w * NCOL))[lane];  // self term
        float4 a1 = make_float4(0.f, 0.f, 0.f, 0.f);
        for (int base = rs; base < re; base += 32) {
            int cnt = min(32, re - base);
            int idx = (lane < cnt) ? __ldg(g_csr + base + lane) : 0;
            int k = 0;
            for (; k + 2 <= cnt; k += 2) {
                int s0 = __shfl_sync(0xffffffffu, idx, k);
                int s1 = __shfl_sync(0xffffffffu, idx, k + 1);
                float4 v0 = ((const float4*)(HT + (size_t)s0 * NCOL))[lane];
                float4 v1 = ((const float4*)(HT + (size_t)s1 * NCOL))[lane];
                a0.x += v0.x; a0.y += v0.y; a0.z += v0.z; a0.w += v0.w;
                a1.x += v1.x; a1.y += v1.y; a1.z += v1.z; a1.w += v1.w;
            }
            if (k < cnt) {
                int s0 = __shfl_sync(0xffffffffu, idx, k);
                float4 v0 = ((const float4*)(HT + (size_t)s0 * NCOL))[lane];
                a0.x += v0.x; a0.y += v0.y; a0.z += v0.z; a0.w += v0.w;
            }
        }
        float4 r = make_float4((a0.x + a1.x) * dv, (a0.y + a1.y) * dv,
                               (a0.z + a1.z) * dv, (a0.w + a1.w) * dv);
        ((float4*)(OUT + (size_t)w * NCOL))[lane] = r;
    } else {
        float2 a0 = ((const float2*)(HT + (size_t)w * NCOL))[lane];
        float2 a1 = make_float2(0.f, 0.f);
        for (int base = rs; base < re; base += 32) {
            int cnt = min(32, re - base);
            int idx = (lane < cnt) ? __ldg(g_csr + base + lane) : 0;
            int k = 0;
            for (; k + 2 <= cnt; k += 2) {
                int s0 = __shfl_sync(0xffffffffu, idx, k);
                int s1 = __shfl_sync(0xffffffffu, idx, k + 1);
                float2 v0 = ((const float2*)(HT + (size_t)s0 * NCOL))[lane];
                float2 v1 = ((const float2*)(HT + (size_t)s1 * NCOL))[lane];
                a0.x += v0.x; a0.y += v0.y;
                a1.x += v1.x; a1.y += v1.y;
            }
            if (k < cnt) {
                int s0 = __shfl_sync(0xffffffffu, idx, k);
                float2 v0 = ((const float2*)(HT + (size_t)s0 * NCOL))[lane];
                a0.x += v0.x; a0.y += v0.y;
            }
        }
        float2 r = make_float2((a0.x + a1.x) * dv, (a0.y + a1.y) * dv);
        float2 bb = ((const float2*)bias)[lane];
        r.x = fmaxf(r.x + bb.x, 0.f);
        r.y = fmaxf(r.y + bb.y, 0.f);
        ((float2*)(OUT + (size_t)w * NCOL))[lane] = r;
    }
}

// ---------------------------------------------------------------------------
extern "C" void kernel_launch(void* const* d_in, const int* in_sizes, int n_in,
                              void* d_out, int out_size)
{
    const float* x  = (const float*)d_in[0];
    const int*   ei = (const int*)  d_in[1];
    const float* W1 = (const float*)d_in[2];
    const float* b1 = (const float*)d_in[3];
    const float* W2 = (const float*)d_in[4];
    const float* b2 = (const float*)d_in[5];
    float* out = (float*)d_out;

    const int n  = in_sizes[0] / DIN;    // 50000
    const int ne = in_sizes[1] / 2;      // 800000
    const int* src = ei;
    const int* dst = ei + ne;

    const int nb_n = (n + 255) / 256;
    const int nb_e = (ne + 255) / 256;
    const int nb_g = (n + 127) / 128;
    const int nb_w = (n + 7) / 8;        // warp per node
    const int nb_sc = (n + 1023) / 1024; // scan blocks (<=64)

    // CSR build
    k_zero<<<nb_n, 256>>>(n);
    k_count<<<nb_e, 256>>>(dst, ne);
    k_scan1<<<nb_sc, 1024>>>(n);         // scan stage 1 + dinv (fused)
    k_scan2<<<1, 32>>>(nb_sc, n);
    k_scan3<<<nb_n, 256>>>(n);
    k_fill<<<nb_e, 256>>>(src, dst, ne);

    // Layer 1
    k_gemm<1><<<nb_g, 256>>>(x, W1, nullptr, n);       // g_ht1 = (x@W1)*dinv
    k_gather<1><<<nb_w, 256>>>(nullptr, nullptr, n);   // g_agg1

    // Layer 2 (gather writes final output: +b2, relu)
    k_gemm<2><<<nb_g, 256>>>(nullptr, W2, b1, n);      // g_ht2
    k_gather<2><<<nb_w, 256>>>(out, b2, n);            // out
}

// round 11
// speedup vs baseline: 2.7280x; 1.0887x over previous
#include <cuda_runtime.h>
#include <cuda_fp16.h>
#include <cstdint>
#include <cstddef>

// Problem constants (reference: N=50000, E=800000, 128->128->64)
#define MAXN 50048
#define MAXE 800000
#define DIN  128
#define DHID 128
#define DOUT 64

// Scratch (static device globals -- no allocation anywhere).
// Only referenced from device code (host can't take __device__ addresses).
__device__ __half g_ht1[(size_t)MAXN * DHID];   // fp16: (x @ W1) * dinv[row]
__device__ __half g_ht2[(size_t)MAXN * DOUT];   // fp16: (relu(agg1+b1) @ W2) * dinv[row]
__device__ float  g_agg1[(size_t)MAXN * DHID];  // fp32: layer-1 aggregated output
__device__ float  g_dinv[MAXN];
__device__ int    g_deg [MAXN];
__device__ int    g_rows[MAXN + 1];             // CSR row starts
__device__ int    g_cur [MAXN];                 // fill cursors
__device__ int    g_bsum[64];                   // scan block sums
__device__ int    g_csr [MAXE];                 // src node per CSR slot

// ---------------------------------------------------------------------------
// Degree / normalization / CSR build
// ---------------------------------------------------------------------------
__global__ void k_zero(int n) {
    int i = blockIdx.x * blockDim.x + threadIdx.x;
    if (i < n) g_deg[i] = 0;
}

__global__ void k_count(const int* __restrict__ dst, int ne) {
    int e = blockIdx.x * blockDim.x + threadIdx.x;
    if (e < ne) atomicAdd(&g_deg[__ldg(dst + e)], 1);
}

// Stage 1: per-1024-block scan of g_deg; also computes g_dinv (fused).
__global__ void k_scan1(int n) {
    __shared__ int s[1024];
    int tid = threadIdx.x;
    int i = blockIdx.x * 1024 + tid;
    int v = (i < n) ? g_deg[i] : 0;
    if (i < n) g_dinv[i] = rsqrtf((float)v + 1.0f);
    s[tid] = v;
    __syncthreads();
    for (int o = 1; o < 1024; o <<= 1) {
        int t = (tid >= o) ? s[tid - o] : 0;
        __syncthreads();
        s[tid] += t;
        __syncthreads();
    }
    if (i < n) g_rows[i] = s[tid] - v;           // exclusive within block
    if (tid == 1023) g_bsum[blockIdx.x] = s[1023];
}

// Stage 2 (fused): each block prefix-sums the <=64 block sums in smem, then
// adds its offset. Also inits cursors and writes g_rows[n] = ne.
__global__ void k_scan3(int n, int nb, int ne) {
    __shared__ int pb[65];
    int tid = threadIdx.x;
    if (tid <= 64) pb[tid] = 0;
    __syncthreads();
    if (tid == 0) {
        int run = 0;
        for (int b = 0; b < nb; b++) { pb[b] = run; run += g_bsum[b]; }
    }
    __syncthreads();
    int i = blockIdx.x * blockDim.x + tid;
    if (i < n) {
        int r = g_rows[i] + pb[i >> 10];
        g_rows[i] = r;
        g_cur[i] = r;
    }
    if (i == 0) g_rows[n] = ne;
}

__global__ void k_fill(const int* __restrict__ src, const int* __restrict__ dst, int ne) {
    int e = blockIdx.x * blockDim.x + threadIdx.x;
    if (e < ne) {
        int d = __ldg(dst + e);
        int pos = atomicAdd(&g_cur[d], 1);
        g_csr[pos] = __ldg(src + e);
    }
}

// ---------------------------------------------------------------------------
// tf32 helpers
// ---------------------------------------------------------------------------
__device__ __forceinline__ uint32_t f2tf32(float f) {
    uint32_t r;
    asm("cvt.rna.tf32.f32 %0, %1;" : "=r"(r) : "f"(f));
    return r;
}

__device__ __forceinline__ void mma_tf32(float c[4],
    uint32_t a0, uint32_t a1, uint32_t a2, uint32_t a3,
    uint32_t b0, uint32_t b1)
{
    asm volatile(
        "mma.sync.aligned.m16n8k8.row.col.f32.tf32.tf32.f32 "
        "{%0,%1,%2,%3}, {%4,%5,%6,%7}, {%8,%9}, {%0,%1,%2,%3};"
        : "+f"(c[0]), "+f"(c[1]), "+f"(c[2]), "+f"(c[3])
        : "r"(a0), "r"(a1), "r"(a2), "r"(a3), "r"(b0), "r"(b1));
}

// ---------------------------------------------------------------------------
// Tensor-core GEMM: HT[n, NCOL] = fp16( (A[n,128] @ B[128, NCOL]) * dinv[row] )
//   LAYER==1: A = x (param)          -> g_ht1
//   LAYER==2: A = relu(g_agg1 + b1)  -> g_ht2
// 256 threads = 8 warps (2m x 4n). CTA tile 128 x NCOL; warp tile 64 x NCOL/4.
// mma.m16n8k8 tf32; K chunked by 32 (4 chunks).
// ---------------------------------------------------------------------------
template <int LAYER>
__global__ void __launch_bounds__(256, 2) k_gemm(
    const float* __restrict__ A_in, const float* __restrict__ B,
    const float* __restrict__ biasA, int n)
{
    constexpr int NCOL = (LAYER == 1) ? DHID : DOUT;
    constexpr bool ACT = (LAYER == 2);
    constexpr int BM = 128;
    constexpr int WN = NCOL / 4;             // warp n-tile: 32 or 16
    constexpr int MA = 4;                    // m16 atoms per warp (64/16)
    constexpr int NA = WN / 8;               // n8 atoms per warp: 4 or 2
    constexpr int BSTRIDE = NCOL + 8;        // bank-free B fragment loads

    const float* A = (LAYER == 1) ? A_in : (const float*)g_agg1;
    __half* HT = (LAYER == 1) ? g_ht1 : g_ht2;

    __shared__ uint32_t As[BM][36];          // tf32 bits; bank = (4r+c)%32
    __shared__ uint32_t Bs[32][BSTRIDE];     // tf32 bits; bank = (8k+c)%32

    const int tid  = threadIdx.x;
    const int wid  = tid >> 5;
    const int lane = tid & 31;
    const int g    = lane >> 2;              // group id (0..7)
    const int tg   = lane & 3;               // thread-in-group (0..3)
    const int warp_m = (wid >> 2) * 64;      // 0 or 64
    const int warp_n = (wid & 3) * WN;
    const int row0 = blockIdx.x * BM;

    float acc[MA][NA][4];
#pragma unroll
    for (int am = 0; am < MA; am++)
#pragma unroll
        for (int an = 0; an < NA; an++)
#pragma unroll
            for (int i = 0; i < 4; i++) acc[am][an][i] = 0.0f;

#pragma unroll 1
    for (int kc = 0; kc < 4; kc++) {
        // Stage A chunk: 128 rows x 32 k (1024 float4, 4 per thread), tf32-convert
#pragma unroll
        for (int i = tid; i < BM * 8; i += 256) {
            int r = i >> 3, c4 = i & 7;
            int grow = row0 + r;
            float4 v = make_float4(0.f, 0.f, 0.f, 0.f);
            if (grow < n) {
                v = ((const float4*)(A + (size_t)grow * 128))[kc * 8 + c4];
                if (ACT) {
                    float4 bb = ((const float4*)biasA)[kc * 8 + c4];
                    v.x = fmaxf(v.x + bb.x, 0.f);
                    v.y = fmaxf(v.y + bb.y, 0.f);
                    v.z = fmaxf(v.z + bb.z, 0.f);
                    v.w = fmaxf(v.w + bb.w, 0.f);
                }
            }
            uint4 t;
            t.x = f2tf32(v.x); t.y = f2tf32(v.y);
            t.z = f2tf32(v.z); t.w = f2tf32(v.w);
            ((uint4*)&As[r][0])[c4] = t;
        }
        // Stage B chunk: 32 x NCOL, tf32-convert
        constexpr int NV = 32 * NCOL / 4;
#pragma unroll
        for (int i = tid; i < NV; i += 256) {
            int k = i / (NCOL / 4), c = i % (NCOL / 4);
            float4 v = ((const float4*)(B + (size_t)(kc * 32 + k) * NCOL))[c];
            uint4 t;
            t.x = f2tf32(v.x); t.y = f2tf32(v.y);
            t.z = f2tf32(v.z); t.w = f2tf32(v.w);
            ((uint4*)&Bs[k][0])[c] = t;
        }
        __syncthreads();

#pragma unroll
        for (int ks = 0; ks < 4; ks++) {
            const int k0 = ks * 8;
            uint32_t af[MA][4];
#pragma unroll
            for (int am = 0; am < MA; am++) {
                int r = warp_m + am * 16 + g;
                af[am][0] = As[r]    [k0 + tg];
                af[am][1] = As[r + 8][k0 + tg];
                af[am][2] = As[r]    [k0 + tg + 4];
                af[am][3] = As[r + 8][k0 + tg + 4];
            }
            uint32_t bf[NA][2];
#pragma unroll
            for (int an = 0; an < NA; an++) {
                int c = warp_n + an * 8 + g;
                bf[an][0] = Bs[k0 + tg]    [c];
                bf[an][1] = Bs[k0 + tg + 4][c];
            }
#pragma unroll
            for (int am = 0; am < MA; am++)
#pragma unroll
                for (int an = 0; an < NA; an++)
                    mma_tf32(acc[am][an], af[am][0], af[am][1], af[am][2],
                             af[am][3], bf[an][0], bf[an][1]);
        }
        __syncthreads();
    }

    // Epilogue: HT = fp16(acc * dinv[row])
#pragma unroll
    for (int am = 0; am < MA; am++) {
        int r_lo = row0 + warp_m + am * 16 + g;
        int r_hi = r_lo + 8;
        float dv_lo = (r_lo < n) ? g_dinv[r_lo] : 0.f;
        float dv_hi = (r_hi < n) ? g_dinv[r_hi] : 0.f;
#pragma unroll
        for (int an = 0; an < NA; an++) {
            int col = warp_n + an * 8 + tg * 2;
            if (r_lo < n) {
                *(__half2*)(HT + (size_t)r_lo * NCOL + col) =
                    __floats2half2_rn(acc[am][an][0] * dv_lo,
                                      acc[am][an][1] * dv_lo);
            }
            if (r_hi < n) {
                *(__half2*)(HT + (size_t)r_hi * NCOL + col) =
                    __floats2half2_rn(acc[am][an][2] * dv_hi,
                                      acc[am][an][3] * dv_hi);
            }
        }
    }
}

// ---------------------------------------------------------------------------
// CSR gather (fp16 source rows, fp32 accumulation): one warp per node.
//   out[d] = dinv[d] * (ht[d] + sum_{s in N(d)} ht[s])   [+ bias, relu if LAYER==2]
// LAYER==1: HT=g_ht1 (128 cols, lane covers 4), OUT=g_agg1 (fp32)
// LAYER==2: HT=g_ht2 (64 cols, lane covers 2),  OUT=out_param (+b2, relu)
// ---------------------------------------------------------------------------
template <int LAYER>
__global__ void __launch_bounds__(256) k_gather(
    float* __restrict__ out_param, const float* __restrict__ bias, int n)
{
    constexpr int NCOL = (LAYER == 1) ? DHID : DOUT;
    const __half* HT = (LAYER == 1) ? g_ht1 : g_ht2;
    float* OUT = (LAYER == 1) ? g_agg1 : out_param;

    int w = (blockIdx.x * 256 + threadIdx.x) >> 5;
    int lane = threadIdx.x & 31;
    if (w >= n) return;

    int rs = 0, re = 0;
    float dv = 0.f;
    if (lane == 0) {
        rs = g_rows[w];
        re = g_rows[w + 1];
        dv = g_dinv[w];
    }
    rs = __shfl_sync(0xffffffffu, rs, 0);
    re = __shfl_sync(0xffffffffu, re, 0);
    dv = __shfl_sync(0xffffffffu, dv, 0);

    if (LAYER == 1) {
        // lane covers cols [lane*4, lane*4+4): two half2 = one 8B load per row
        const __half2* self = (const __half2*)(HT + (size_t)w * NCOL);
        float2 s0 = __half22float2(self[lane * 2]);
        float2 s1 = __half22float2(self[lane * 2 + 1]);
        float4 a0 = make_float4(s0.x, s0.y, s1.x, s1.y);
        float4 a1 = make_float4(0.f, 0.f, 0.f, 0.f);
        for (int base = rs; base < re; base += 32) {
            int cnt = min(32, re - base);
            int idx = (lane < cnt) ? __ldg(g_csr + base + lane) : 0;
            int k = 0;
            for (; k + 2 <= cnt; k += 2) {
                int n0 = __shfl_sync(0xffffffffu, idx, k);
                int n1 = __shfl_sync(0xffffffffu, idx, k + 1);
                uint2 r0 = ((const uint2*)(HT + (size_t)n0 * NCOL))[lane];
                uint2 r1 = ((const uint2*)(HT + (size_t)n1 * NCOL))[lane];
                float2 p0 = __half22float2(*(__half2*)&r0.x);
                float2 p1 = __half22float2(*(__half2*)&r0.y);
                float2 q0 = __half22float2(*(__half2*)&r1.x);
                float2 q1 = __half22float2(*(__half2*)&r1.y);
                a0.x += p0.x; a0.y += p0.y; a0.z += p1.x; a0.w += p1.y;
                a1.x += q0.x; a1.y += q0.y; a1.z += q1.x; a1.w += q1.y;
            }
            if (k < cnt) {
                int n0 = __shfl_sync(0xffffffffu, idx, k);
                uint2 r0 = ((const uint2*)(HT + (size_t)n0 * NCOL))[lane];
                float2 p0 = __half22float2(*(__half2*)&r0.x);
                float2 p1 = __half22float2(*(__half2*)&r0.y);
                a0.x += p0.x; a0.y += p0.y; a0.z += p1.x; a0.w += p1.y;
            }
        }
        float4 r = make_float4((a0.x + a1.x) * dv, (a0.y + a1.y) * dv,
                               (a0.z + a1.z) * dv, (a0.w + a1.w) * dv);
        ((float4*)(OUT + (size_t)w * NCOL))[lane] = r;
    } else {
        // lane covers cols [lane*2, lane*2+2): one half2 per row
        const __half2* self = (const __half2*)(HT + (size_t)w * NCOL);
        float2 a0 = __half22float2(self[lane]);
        float2 a1 = make_float2(0.f, 0.f);
        for (int base = rs; base < re; base += 32) {
            int cnt = min(32, re - base);
            int idx = (lane < cnt) ? __ldg(g_csr + base + lane) : 0;
            int k = 0;
            for (; k + 2 <= cnt; k += 2) {
                int n0 = __shfl_sync(0xffffffffu, idx, k);
                int n1 = __shfl_sync(0xffffffffu, idx, k + 1);
                float2 p = __half22float2(((const __half2*)(HT + (size_t)n0 * NCOL))[lane]);
                float2 q = __half22float2(((const __half2*)(HT + (size_t)n1 * NCOL))[lane]);
                a0.x += p.x; a0.y += p.y;
                a1.x += q.x; a1.y += q.y;
            }
            if (k < cnt) {
                int n0 = __shfl_sync(0xffffffffu, idx, k);
                float2 p = __half22float2(((const __half2*)(HT + (size_t)n0 * NCOL))[lane]);
                a0.x += p.x; a0.y += p.y;
            }
        }
        float2 r = make_float2((a0.x + a1.x) * dv, (a0.y + a1.y) * dv);
        float2 bb = ((const float2*)bias)[lane];
        r.x = fmaxf(r.x + bb.x, 0.f);
        r.y = fmaxf(r.y + bb.y, 0.f);
        ((float2*)(OUT + (size_t)w * NCOL))[lane] = r;
    }
}

// ---------------------------------------------------------------------------
extern "C" void kernel_launch(void* const* d_in, const int* in_sizes, int n_in,
                              void* d_out, int out_size)
{
    const float* x  = (const float*)d_in[0];
    const int*   ei = (const int*)  d_in[1];
    const float* W1 = (const float*)d_in[2];
    const float* b1 = (const float*)d_in[3];
    const float* W2 = (const float*)d_in[4];
    const float* b2 = (const float*)d_in[5];
    float* out = (float*)d_out;

    const int n  = in_sizes[0] / DIN;    // 50000
    const int ne = in_sizes[1] / 2;      // 800000
    const int* src = ei;
    const int* dst = ei + ne;

    const int nb_n = (n + 255) / 256;
    const int nb_e = (ne + 255) / 256;
    const int nb_g = (n + 127) / 128;
    const int nb_w = (n + 7) / 8;        // warp per node
    const int nb_sc = (n + 1023) / 1024; // scan blocks (<=64)

    // CSR build
    k_zero<<<nb_n, 256>>>(n);
    k_count<<<nb_e, 256>>>(dst, ne);
    k_scan1<<<nb_sc, 1024>>>(n);             // block scan + dinv
    k_scan3<<<nb_n, 256>>>(n, nb_sc, ne);    // block-sum prefix + offsets + cursors
    k_fill<<<nb_e, 256>>>(src, dst, ne);

    // Layer 1
    k_gemm<1><<<nb_g, 256>>>(x, W1, nullptr, n);       // g_ht1 (fp16)
    k_gather<1><<<nb_w, 256>>>(nullptr, nullptr, n);   // g_agg1 (fp32)

    // Layer 2 (gather writes final output: +b2, relu)
    k_gemm<2><<<nb_g, 256>>>(nullptr, W2, b1, n);      // g_ht2 (fp16)
    k_gather<2><<<nb_w, 256>>>(out, b2, n);            // out
}

// round 15
// speedup vs baseline: 2.8824x; 1.0566x over previous
#include <cuda_runtime.h>
#include <cuda_fp16.h>
#include <cstdint>
#include <cstddef>

// Problem constants (reference: N=50000, E=800000, 128->128->64)
#define MAXN 50048
#define MAXE 800000
#define DIN  128
#define DHID 128
#define DOUT 64

// Scratch (static device globals -- no allocation anywhere).
// Only referenced from device code (host can't take __device__ addresses).
__device__ __half g_ht1 [(size_t)MAXN * DHID];  // fp16: (x @ W1) * dinv[row]
__device__ __half g_agg1[(size_t)MAXN * DHID];  // fp16: relu(layer-1 output + b1)
__device__ __half g_ht2 [(size_t)MAXN * DOUT];  // fp16: (agg1 @ W2) * dinv[row]
__device__ float  g_dinv[MAXN];
__device__ int    g_deg [MAXN];
__device__ int    g_rows[MAXN + 1];             // CSR row starts
__device__ int    g_cur [MAXN];                 // fill cursors
__device__ int    g_bsum[64];                   // scan block sums
__device__ int    g_csr [MAXE];                 // src node per CSR slot

// ---------------------------------------------------------------------------
// Degree / normalization / CSR build
// ---------------------------------------------------------------------------
__global__ void k_zero(int n) {
    int i = blockIdx.x * blockDim.x + threadIdx.x;
    if (i < n) g_deg[i] = 0;
}

// 4 edges per thread (int4 loads)
__global__ void k_count(const int* __restrict__ dst, int ne) {
    int t = blockIdx.x * blockDim.x + threadIdx.x;
    int e = t * 4;
    if (e + 3 < ne) {
        int4 d = *(const int4*)(dst + e);
        atomicAdd(&g_deg[d.x], 1);
        atomicAdd(&g_deg[d.y], 1);
        atomicAdd(&g_deg[d.z], 1);
        atomicAdd(&g_deg[d.w], 1);
    } else {
        for (; e < ne; e++) atomicAdd(&g_deg[__ldg(dst + e)], 1);
    }
}

// Stage 1: per-1024-block scan of g_deg; also computes g_dinv (fused).
__global__ void k_scan1(int n) {
    __shared__ int s[1024];
    int tid = threadIdx.x;
    int i = blockIdx.x * 1024 + tid;
    int v = (i < n) ? g_deg[i] : 0;
    if (i < n) g_dinv[i] = rsqrtf((float)v + 1.0f);
    s[tid] = v;
    __syncthreads();
    for (int o = 1; o < 1024; o <<= 1) {
        int t = (tid >= o) ? s[tid - o] : 0;
        __syncthreads();
        s[tid] += t;
        __syncthreads();
    }
    if (i < n) g_rows[i] = s[tid] - v;           // exclusive within block
    if (tid == 1023) g_bsum[blockIdx.x] = s[1023];
}

// Stage 2: cooperative block-sum scan (parallel loads + log-step smem scan),
// then add block offsets; init cursors; write g_rows[n] = ne.
__global__ void k_scan3(int n, int nb, int ne) {
    __shared__ int sb[64];
    int tid = threadIdx.x;
    if (tid < 64) sb[tid] = (tid < nb) ? g_bsum[tid] : 0;
    __syncthreads();
#pragma unroll
    for (int o = 1; o < 64; o <<= 1) {
        int t = 0;
        if (tid < 64 && tid >= o) t = sb[tid - o];
        __syncthreads();
        if (tid < 64) sb[tid] += t;              // inclusive scan
        __syncthreads();
    }
    int i = blockIdx.x * blockDim.x + tid;
    if (i < n) {
        int b = i >> 10;
        int off = (b == 0) ? 0 : sb[b - 1];      // exclusive offset
        int r = g_rows[i] + off;
        g_rows[i] = r;
        g_cur[i] = r;
    }
    if (i == 0) g_rows[n] = ne;
}

// 4 edges per thread (int4 loads)
__global__ void k_fill(const int* __restrict__ src, const int* __restrict__ dst, int ne) {
    int t = blockIdx.x * blockDim.x + threadIdx.x;
    int e = t * 4;
    if (e + 3 < ne) {
        int4 d = *(const int4*)(dst + e);
        int4 s = *(const int4*)(src + e);
        g_csr[atomicAdd(&g_cur[d.x], 1)] = s.x;
        g_csr[atomicAdd(&g_cur[d.y], 1)] = s.y;
        g_csr[atomicAdd(&g_cur[d.z], 1)] = s.z;
        g_csr[atomicAdd(&g_cur[d.w], 1)] = s.w;
    } else {
        for (; e < ne; e++) {
            int d = __ldg(dst + e);
            g_csr[atomicAdd(&g_cur[d], 1)] = __ldg(src + e);
        }
    }
}

// ---------------------------------------------------------------------------
// tf32 helpers
// ---------------------------------------------------------------------------
__device__ __forceinline__ uint32_t f2tf32(float f) {
    uint32_t r;
    asm("cvt.rna.tf32.f32 %0, %1;" : "=r"(r) : "f"(f));
    return r;
}

__device__ __forceinline__ void mma_tf32(float c[4],
    uint32_t a0, uint32_t a1, uint32_t a2, uint32_t a3,
    uint32_t b0, uint32_t b1)
{
    asm volatile(
        "mma.sync.aligned.m16n8k8.row.col.f32.tf32.tf32.f32 "
        "{%0,%1,%2,%3}, {%4,%5,%6,%7}, {%8,%9}, {%0,%1,%2,%3};"
        : "+f"(c[0]), "+f"(c[1]), "+f"(c[2]), "+f"(c[3])
        : "r"(a0), "r"(a1), "r"(a2), "r"(a3), "r"(b0), "r"(b1));
}

// ---------------------------------------------------------------------------
// Tensor-core GEMM: HT[n, NCOL] = fp16( (A[n,128] @ B[128, NCOL]) * dinv[row] )
//   LAYER==1: A = x (fp32 param)          -> g_ht1
//   LAYER==2: A = g_agg1 (fp16, pre-activated) -> g_ht2
// 256 threads = 8 warps (2m x 4n). CTA tile 128 x NCOL; warp tile 64 x NCOL/4.
// mma.m16n8k8 tf32; K chunked by 32 (4 chunks).
// ---------------------------------------------------------------------------
template <int LAYER>
__global__ void __launch_bounds__(256, 2) k_gemm(
    const float* __restrict__ A_in, const float* __restrict__ B, int n)
{
    constexpr int NCOL = (LAYER == 1) ? DHID : DOUT;
    constexpr int BM = 128;
    constexpr int WN = NCOL / 4;             // warp n-tile: 32 or 16
    constexpr int MA = 4;                    // m16 atoms per warp (64/16)
    constexpr int NA = WN / 8;               // n8 atoms per warp: 4 or 2
    constexpr int BSTRIDE = NCOL + 8;        // bank-free B fragment loads

    __half* HT = (LAYER == 1) ? g_ht1 : g_ht2;

    __shared__ uint32_t As[BM][36];          // tf32 bits; bank = (4r+c)%32
    __shared__ uint32_t Bs[32][BSTRIDE];     // tf32 bits; bank = (8k+c)%32

    const int tid  = threadIdx.x;
    const int wid  = tid >> 5;
    const int lane = tid & 31;
    const int g    = lane >> 2;              // group id (0..7)
    const int tg   = lane & 3;               // thread-in-group (0..3)
    const int warp_m = (wid >> 2) * 64;      // 0 or 64
    const int warp_n = (wid & 3) * WN;
    const int row0 = blockIdx.x * BM;

    float acc[MA][NA][4];
#pragma unroll
    for (int am = 0; am < MA; am++)
#pragma unroll
        for (int an = 0; an < NA; an++)
#pragma unroll
            for (int i = 0; i < 4; i++) acc[am][an][i] = 0.0f;

#pragma unroll 1
    for (int kc = 0; kc < 4; kc++) {
        // Stage A chunk: 128 rows x 32 k (4 cols per slot, 8 slots per row)
#pragma unroll
        for (int i = tid; i < BM * 8; i += 256) {
            int r = i >> 3, c4 = i & 7;
            int grow = row0 + r;
            float4 v = make_float4(0.f, 0.f, 0.f, 0.f);
            if (grow < n) {
                if (LAYER == 1) {
                    v = ((const float4*)(A_in + (size_t)grow * 128))[kc * 8 + c4];
                } else {
                    // fp16 pre-activated agg1: 4 halfs = uint2
                    uint2 hv = *(const uint2*)(g_agg1 + (size_t)grow * 128 + kc * 32 + c4 * 4);
                    float2 p0 = __half22float2(*(__half2*)&hv.x);
                    float2 p1 = __half22float2(*(__half2*)&hv.y);
                    v = make_float4(p0.x, p0.y, p1.x, p1.y);
                }
            }
            uint4 t;
            t.x = f2tf32(v.x); t.y = f2tf32(v.y);
            t.z = f2tf32(v.z); t.w = f2tf32(v.w);
            ((uint4*)&As[r][0])[c4] = t;
        }
        // Stage B chunk: 32 x NCOL, tf32-convert
        constexpr int NV = 32 * NCOL / 4;
#pragma unroll
        for (int i = tid; i < NV; i += 256) {
            int k = i / (NCOL / 4), c = i % (NCOL / 4);
            float4 v = ((const float4*)(B + (size_t)(kc * 32 + k) * NCOL))[c];
            uint4 t;
            t.x = f2tf32(v.x); t.y = f2tf32(v.y);
            t.z = f2tf32(v.z); t.w = f2tf32(v.w);
            ((uint4*)&Bs[k][0])[c] = t;
        }
        __syncthreads();

#pragma unroll
        for (int ks = 0; ks < 4; ks++) {
            const int k0 = ks * 8;
            uint32_t af[MA][4];
#pragma unroll
            for (int am = 0; am < MA; am++) {
                int r = warp_m + am * 16 + g;
                af[am][0] = As[r]    [k0 + tg];
                af[am][1] = As[r + 8][k0 + tg];
                af[am][2] = As[r]    [k0 + tg + 4];
                af[am][3] = As[r + 8][k0 + tg + 4];
            }
            uint32_t bf[NA][2];
#pragma unroll
            for (int an = 0; an < NA; an++) {
                int c = warp_n + an * 8 + g;
                bf[an][0] = Bs[k0 + tg]    [c];
                bf[an][1] = Bs[k0 + tg + 4][c];
            }
#pragma unroll
            for (int am = 0; am < MA; am++)
#pragma unroll
                for (int an = 0; an < NA; an++)
                    mma_tf32(acc[am][an], af[am][0], af[am][1], af[am][2],
                             af[am][3], bf[an][0], bf[an][1]);
        }
        __syncthreads();
    }

    // Epilogue: HT = fp16(acc * dinv[row])
#pragma unroll
    for (int am = 0; am < MA; am++) {
        int r_lo = row0 + warp_m + am * 16 + g;
        int r_hi = r_lo + 8;
        float dv_lo = (r_lo < n) ? g_dinv[r_lo] : 0.f;
        float dv_hi = (r_hi < n) ? g_dinv[r_hi] : 0.f;
#pragma unroll
        for (int an = 0; an < NA; an++) {
            int col = warp_n + an * 8 + tg * 2;
            if (r_lo < n) {
                *(__half2*)(HT + (size_t)r_lo * NCOL + col) =
                    __floats2half2_rn(acc[am][an][0] * dv_lo,
                                      acc[am][an][1] * dv_lo);
            }
            if (r_hi < n) {
                *(__half2*)(HT + (size_t)r_hi * NCOL + col) =
                    __floats2half2_rn(acc[am][an][2] * dv_hi,
                                      acc[am][an][3] * dv_hi);
            }
        }
    }
}

// ---------------------------------------------------------------------------
// CSR gather (fp16 source rows, fp32 accumulation): one warp per node.
// LAYER==1: agg1[d] = fp16( relu( dinv[d]*(ht1[d] + sum ht1[s]) + b1 ) )
// LAYER==2: out [d] =        relu( dinv[d]*(ht2[d] + sum ht2[s]) + b2 )  (fp32)
// ---------------------------------------------------------------------------
template <int LAYER>
__global__ void __launch_bounds__(256) k_gather(
    float* __restrict__ out_param, const float* __restrict__ bias, int n)
{
    constexpr int NCOL = (LAYER == 1) ? DHID : DOUT;
    const __half* HT = (LAYER == 1) ? g_ht1 : g_ht2;

    int w = (blockIdx.x * 256 + threadIdx.x) >> 5;
    int lane = threadIdx.x & 31;
    if (w >= n) return;

    int rs = 0, re = 0;
    float dv = 0.f;
    if (lane == 0) {
        rs = g_rows[w];
        re = g_rows[w + 1];
        dv = g_dinv[w];
    }
    rs = __shfl_sync(0xffffffffu, rs, 0);
    re = __shfl_sync(0xffffffffu, re, 0);
    dv = __shfl_sync(0xffffffffu, dv, 0);

    if (LAYER == 1) {
        // lane covers cols [lane*4, lane*4+4): one uint2 (8B) load per row
        uint2 sr = ((const uint2*)(HT + (size_t)w * NCOL))[lane];
        float2 s0 = __half22float2(*(__half2*)&sr.x);
        float2 s1 = __half22float2(*(__half2*)&sr.y);
        float4 a0 = make_float4(s0.x, s0.y, s1.x, s1.y);
        float4 a1 = make_float4(0.f, 0.f, 0.f, 0.f);
        for (int base = rs; base < re; base += 32) {
            int cnt = min(32, re - base);
            int idx = (lane < cnt) ? __ldg(g_csr + base + lane) : 0;
            int k = 0;
            for (; k + 2 <= cnt; k += 2) {
                int n0 = __shfl_sync(0xffffffffu, idx, k);
                int n1 = __shfl_sync(0xffffffffu, idx, k + 1);
                uint2 r0 = ((const uint2*)(HT + (size_t)n0 * NCOL))[lane];
                uint2 r1 = ((const uint2*)(HT + (size_t)n1 * NCOL))[lane];
                float2 p0 = __half22float2(*(__half2*)&r0.x);
                float2 p1 = __half22float2(*(__half2*)&r0.y);
                float2 q0 = __half22float2(*(__half2*)&r1.x);
                float2 q1 = __half22float2(*(__half2*)&r1.y);
                a0.x += p0.x; a0.y += p0.y; a0.z += p1.x; a0.w += p1.y;
                a1.x += q0.x; a1.y += q0.y; a1.z += q1.x; a1.w += q1.y;
            }
            if (k < cnt) {
                int n0 = __shfl_sync(0xffffffffu, idx, k);
                uint2 r0 = ((const uint2*)(HT + (size_t)n0 * NCOL))[lane];
                float2 p0 = __half22float2(*(__half2*)&r0.x);
                float2 p1 = __half22float2(*(__half2*)&r0.y);
                a0.x += p0.x; a0.y += p0.y; a0.z += p1.x; a0.w += p1.y;
            }
        }
        // epilogue: * dinv, + b1, relu, fp16 store
        float4 bb = ((const float4*)bias)[lane];
        float rx = fmaxf((a0.x + a1.x) * dv + bb.x, 0.f);
        float ry = fmaxf((a0.y + a1.y) * dv + bb.y, 0.f);
        float rz = fmaxf((a0.z + a1.z) * dv + bb.z, 0.f);
        float rw = fmaxf((a0.w + a1.w) * dv + bb.w, 0.f);
        uint2 st;
        *(__half2*)&st.x = __floats2half2_rn(rx, ry);
        *(__half2*)&st.y = __floats2half2_rn(rz, rw);
        ((uint2*)(g_agg1 + (size_t)w * NCOL))[lane] = st;
    } else {
        // lane covers cols [lane*2, lane*2+2): one half2 per row
        const __half2* self = (const __half2*)(HT + (size_t)w * NCOL);
        float2 a0 = __half22float2(self[lane]);
        float2 a1 = make_float2(0.f, 0.f);
        for (int base = rs; base < re; base += 32) {
            int cnt = min(32, re - base);
            int idx = (lane < cnt) ? __ldg(g_csr + base + lane) : 0;
            int k = 0;
            for (; k + 2 <= cnt; k += 2) {
                int n0 = __shfl_sync(0xffffffffu, idx, k);
                int n1 = __shfl_sync(0xffffffffu, idx, k + 1);
                float2 p = __half22float2(((const __half2*)(HT + (size_t)n0 * NCOL))[lane]);
                float2 q = __half22float2(((const __half2*)(HT + (size_t)n1 * NCOL))[lane]);
                a0.x += p.x; a0.y += p.y;
                a1.x += q.x; a1.y += q.y;
            }
            if (k < cnt) {
                int n0 = __shfl_sync(0xffffffffu, idx, k);
                float2 p = __half22float2(((const __half2*)(HT + (size_t)n0 * NCOL))[lane]);
                a0.x += p.x; a0.y += p.y;
            }
        }
        float2 bb = ((const float2*)bias)[lane];
        float2 r = make_float2(fmaxf((a0.x + a1.x) * dv + bb.x, 0.f),
                               fmaxf((a0.y + a1.y) * dv + bb.y, 0.f));
        ((float2*)(out_param + (size_t)w * NCOL))[lane] = r;
    }
}

// ---------------------------------------------------------------------------
extern "C" void kernel_launch(void* const* d_in, const int* in_sizes, int n_in,
                              void* d_out, int out_size)
{
    const float* x  = (const float*)d_in[0];
    const int*   ei = (const int*)  d_in[1];
    const float* W1 = (const float*)d_in[2];
    const float* b1 = (const float*)d_in[3];
    const float* W2 = (const float*)d_in[4];
    const float* b2 = (const float*)d_in[5];
    float* out = (float*)d_out;

    const int n  = in_sizes[0] / DIN;    // 50000
    const int ne = in_sizes[1] / 2;      // 800000
    const int* src = ei;
    const int* dst = ei + ne;

    const int nb_n = (n + 255) / 256;
    const int nb_e4 = (ne / 4 + 255) / 256;   // 4 edges per thread
    const int nb_g = (n + 127) / 128;
    const int nb_w = (n + 7) / 8;        // warp per node
    const int nb_sc = (n + 1023) / 1024; // scan blocks (<=64)

    // CSR build
    k_zero<<<nb_n, 256>>>(n);
    k_count<<<nb_e4, 256>>>(dst, ne);
    k_scan1<<<nb_sc, 1024>>>(n);             // block scan + dinv
    k_scan3<<<nb_n, 256>>>(n, nb_sc, ne);    // coop block-sum scan + offsets + cursors
    k_fill<<<nb_e4, 256>>>(src, dst, ne);

    // Layer 1
    k_gemm<1><<<nb_g, 256>>>(x, W1, n);      // g_ht1 (fp16)
    k_gather<1><<<nb_w, 256>>>(nullptr, b1, n);  // g_agg1 = fp16(relu(.+b1))

    // Layer 2 (gather writes final output: +b2, relu)
    k_gemm<2><<<nb_g, 256>>>(nullptr, W2, n);    // g_ht2 (fp16)
    k_gather<2><<<nb_w, 256>>>(out, b2, n);      // out (fp32)
}

// round 16
// speedup vs baseline: 3.1219x; 1.0831x over previous
#include <cuda_runtime.h>
#include <cuda_fp16.h>
#include <cstdint>
#include <cstddef>

// Problem constants (reference: N=50000, E=800000, 128->128->64)
#define MAXN 50048
#define MAXE 800000
#define DIN  128
#define DHID 128
#define DOUT 64

// Scratch (static device globals -- no allocation anywhere).
// Only referenced from device code.
__device__ __half g_ht1 [(size_t)MAXN * DHID];  // fp16: x @ W1 (UNSCALED)
__device__ __half g_agg1[(size_t)MAXN * DHID];  // fp16: relu(layer-1 output + b1)
__device__ __half g_ht2 [(size_t)MAXN * DOUT];  // fp16: (agg1 @ W2) * dinv[row]
__device__ float  g_dinv[MAXN];
__device__ int    g_deg [MAXN];
__device__ int    g_rows[MAXN];                 // CSR segment starts (atomic-allocated)
__device__ int    g_cur [MAXN];                 // fill cursors
__device__ int    g_ctr;                        // global segment allocator
__device__ int    g_csr [MAXE];                 // src node per CSR slot

// ---------------------------------------------------------------------------
// CSR build (runs on side stream, overlapped with k_gemm<1>)
// ---------------------------------------------------------------------------
__global__ void k_zero(int n) {
    int i = blockIdx.x * blockDim.x + threadIdx.x;
    if (i < n) g_deg[i] = 0;
    if (i == 0) g_ctr = 0;
}

// 4 edges per thread (int4 loads)
__global__ void k_count(const int* __restrict__ dst, int ne) {
    int t = blockIdx.x * blockDim.x + threadIdx.x;
    int e = t * 4;
    if (e + 3 < ne) {
        int4 d = *(const int4*)(dst + e);
        atomicAdd(&g_deg[d.x], 1);
        atomicAdd(&g_deg[d.y], 1);
        atomicAdd(&g_deg[d.z], 1);
        atomicAdd(&g_deg[d.w], 1);
    } else {
        for (; e < ne; e++) atomicAdd(&g_deg[__ldg(dst + e)], 1);
    }
}

// Segment allocation: block-wide exclusive scan of degrees (shfl) + ONE
// atomicAdd on g_ctr per block. Segment order is arbitrary -- irrelevant,
// each node only needs its own contiguous [rows[i], rows[i]+deg[i]) range.
// Also computes dinv (fused).
__global__ void __launch_bounds__(256) k_alloc(int n) {
    __shared__ int wsum[8];
    __shared__ int sbase;
    int tid = threadIdx.x;
    int lane = tid & 31, wid = tid >> 5;
    int i = blockIdx.x * 256 + tid;
    int v = (i < n) ? g_deg[i] : 0;

    // warp-inclusive scan
    int incl = v;
#pragma unroll
    for (int o = 1; o < 32; o <<= 1) {
        int t = __shfl_up_sync(0xffffffffu, incl, o);
        if (lane >= o) incl += t;
    }
    if (lane == 31) wsum[wid] = incl;
    __syncthreads();
    if (tid < 8) {
        int ws = wsum[tid];
        int incl8 = ws;
#pragma unroll
        for (int o = 1; o < 8; o <<= 1) {
            int t = __shfl_up_sync(0xffu, incl8, o);
            if (tid >= o) incl8 += t;
        }
        wsum[tid] = incl8 - ws;                  // exclusive warp offset
        if (tid == 7) sbase = atomicAdd(&g_ctr, incl8);  // block base
    }
    __syncthreads();
    if (i < n) {
        int r = sbase + wsum[wid] + (incl - v);
        g_rows[i] = r;
        g_cur[i] = r;
        g_dinv[i] = rsqrtf((float)v + 1.0f);
    }
}

// 4 edges per thread (int4 loads)
__global__ void k_fill(const int* __restrict__ src, const int* __restrict__ dst, int ne) {
    int t = blockIdx.x * blockDim.x + threadIdx.x;
    int e = t * 4;
    if (e + 3 < ne) {
        int4 d = *(const int4*)(dst + e);
        int4 s = *(const int4*)(src + e);
        g_csr[atomicAdd(&g_cur[d.x], 1)] = s.x;
        g_csr[atomicAdd(&g_cur[d.y], 1)] = s.y;
        g_csr[atomicAdd(&g_cur[d.z], 1)] = s.z;
        g_csr[atomicAdd(&g_cur[d.w], 1)] = s.w;
    } else {
        for (; e < ne; e++) {
            int d = __ldg(dst + e);
            g_csr[atomicAdd(&g_cur[d], 1)] = __ldg(src + e);
        }
    }
}

// ---------------------------------------------------------------------------
// tf32 helpers
// ---------------------------------------------------------------------------
__device__ __forceinline__ uint32_t f2tf32(float f) {
    uint32_t r;
    asm("cvt.rna.tf32.f32 %0, %1;" : "=r"(r) : "f"(f));
    return r;
}

__device__ __forceinline__ void mma_tf32(float c[4],
    uint32_t a0, uint32_t a1, uint32_t a2, uint32_t a3,
    uint32_t b0, uint32_t b1)
{
    asm volatile(
        "mma.sync.aligned.m16n8k8.row.col.f32.tf32.tf32.f32 "
        "{%0,%1,%2,%3}, {%4,%5,%6,%7}, {%8,%9}, {%0,%1,%2,%3};"
        : "+f"(c[0]), "+f"(c[1]), "+f"(c[2]), "+f"(c[3])
        : "r"(a0), "r"(a1), "r"(a2), "r"(a3), "r"(b0), "r"(b1));
}

// ---------------------------------------------------------------------------
// Tensor-core GEMM.
//   LAYER==1: ht1 = fp16( x @ W1 )            (UNSCALED -- no dinv dependency,
//                                              so it can run concurrently with
//                                              the CSR build)
//   LAYER==2: ht2 = fp16( (agg1 @ W2) * dinv[row] )
// 256 threads = 8 warps (2m x 4n). CTA tile 128 x NCOL; warp tile 64 x NCOL/4.
// ---------------------------------------------------------------------------
template <int LAYER>
__global__ void __launch_bounds__(256, 2) k_gemm(
    const float* __restrict__ A_in, const float* __restrict__ B, int n)
{
    constexpr int NCOL = (LAYER == 1) ? DHID : DOUT;
    constexpr int BM = 128;
    constexpr int WN = NCOL / 4;             // warp n-tile: 32 or 16
    constexpr int MA = 4;                    // m16 atoms per warp
    constexpr int NA = WN / 8;               // n8 atoms per warp: 4 or 2
    constexpr int BSTRIDE = NCOL + 8;

    __half* HT = (LAYER == 1) ? g_ht1 : g_ht2;

    __shared__ uint32_t As[BM][36];          // tf32 bits; bank = (4r+c)%32
    __shared__ uint32_t Bs[32][BSTRIDE];     // tf32 bits; bank = (8k+c)%32

    const int tid  = threadIdx.x;
    const int wid  = tid >> 5;
    const int lane = tid & 31;
    const int g    = lane >> 2;
    const int tg   = lane & 3;
    const int warp_m = (wid >> 2) * 64;
    const int warp_n = (wid & 3) * WN;
    const int row0 = blockIdx.x * BM;

    float acc[MA][NA][4];
#pragma unroll
    for (int am = 0; am < MA; am++)
#pragma unroll
        for (int an = 0; an < NA; an++)
#pragma unroll
            for (int i = 0; i < 4; i++) acc[am][an][i] = 0.0f;

#pragma unroll 1
    for (int kc = 0; kc < 4; kc++) {
#pragma unroll
        for (int i = tid; i < BM * 8; i += 256) {
            int r = i >> 3, c4 = i & 7;
            int grow = row0 + r;
            float4 v = make_float4(0.f, 0.f, 0.f, 0.f);
            if (grow < n) {
                if (LAYER == 1) {
                    v = ((const float4*)(A_in + (size_t)grow * 128))[kc * 8 + c4];
                } else {
                    uint2 hv = *(const uint2*)(g_agg1 + (size_t)grow * 128 + kc * 32 + c4 * 4);
                    float2 p0 = __half22float2(*(__half2*)&hv.x);
                    float2 p1 = __half22float2(*(__half2*)&hv.y);
                    v = make_float4(p0.x, p0.y, p1.x, p1.y);
                }
            }
            uint4 t;
            t.x = f2tf32(v.x); t.y = f2tf32(v.y);
            t.z = f2tf32(v.z); t.w = f2tf32(v.w);
            ((uint4*)&As[r][0])[c4] = t;
        }
        constexpr int NV = 32 * NCOL / 4;
#pragma unroll
        for (int i = tid; i < NV; i += 256) {
            int k = i / (NCOL / 4), c = i % (NCOL / 4);
            float4 v = ((const float4*)(B + (size_t)(kc * 32 + k) * NCOL))[c];
            uint4 t;
            t.x = f2tf32(v.x); t.y = f2tf32(v.y);
            t.z = f2tf32(v.z); t.w = f2tf32(v.w);
            ((uint4*)&Bs[k][0])[c] = t;
        }
        __syncthreads();

#pragma unroll
        for (int ks = 0; ks < 4; ks++) {
            const int k0 = ks * 8;
            uint32_t af[MA][4];
#pragma unroll
            for (int am = 0; am < MA; am++) {
                int r = warp_m + am * 16 + g;
                af[am][0] = As[r]    [k0 + tg];
                af[am][1] = As[r + 8][k0 + tg];
                af[am][2] = As[r]    [k0 + tg + 4];
                af[am][3] = As[r + 8][k0 + tg + 4];
            }
            uint32_t bf[NA][2];
#pragma unroll
            for (int an = 0; an < NA; an++) {
                int c = warp_n + an * 8 + g;
                bf[an][0] = Bs[k0 + tg]    [c];
                bf[an][1] = Bs[k0 + tg + 4][c];
            }
#pragma unroll
            for (int am = 0; am < MA; am++)
#pragma unroll
                for (int an = 0; an < NA; an++)
                    mma_tf32(acc[am][an], af[am][0], af[am][1], af[am][2],
                             af[am][3], bf[an][0], bf[an][1]);
        }
        __syncthreads();
    }

    // Epilogue: LAYER 1 stores raw; LAYER 2 scales by dinv[row].
#pragma unroll
    for (int am = 0; am < MA; am++) {
        int r_lo = row0 + warp_m + am * 16 + g;
        int r_hi = r_lo + 8;
        float dv_lo = 1.f, dv_hi = 1.f;
        if (LAYER == 2) {
            dv_lo = (r_lo < n) ? g_dinv[r_lo] : 0.f;
            dv_hi = (r_hi < n) ? g_dinv[r_hi] : 0.f;
        }
#pragma unroll
        for (int an = 0; an < NA; an++) {
            int col = warp_n + an * 8 + tg * 2;
            if (r_lo < n) {
                *(__half2*)(HT + (size_t)r_lo * NCOL + col) =
                    __floats2half2_rn(acc[am][an][0] * dv_lo,
                                      acc[am][an][1] * dv_lo);
            }
            if (r_hi < n) {
                *(__half2*)(HT + (size_t)r_hi * NCOL + col) =
                    __floats2half2_rn(acc[am][an][2] * dv_hi,
                                      acc[am][an][3] * dv_hi);
            }
        }
    }
}

// ---------------------------------------------------------------------------
// CSR gather: one warp per node.  re = rs + deg[w].
// LAYER==1 (ht1 unscaled): agg1[d] = fp16(relu( dv*(ht1[d]*dv + sum ht1[s]*dinv[s]) + b1 ))
// LAYER==2 (ht2 scaled):   out [d] =      relu( dv*(ht2[d]    + sum ht2[s])         + b2 )
// ---------------------------------------------------------------------------
template <int LAYER>
__global__ void __launch_bounds__(256) k_gather(
    float* __restrict__ out_param, const float* __restrict__ bias, int n)
{
    constexpr int NCOL = (LAYER == 1) ? DHID : DOUT;
    const __half* HT = (LAYER == 1) ? g_ht1 : g_ht2;

    int w = (blockIdx.x * 256 + threadIdx.x) >> 5;
    int lane = threadIdx.x & 31;
    if (w >= n) return;

    int rs = 0, re = 0;
    float dv = 0.f;
    if (lane == 0) {
        rs = g_rows[w];
        re = rs + g_deg[w];
        dv = g_dinv[w];
    }
    rs = __shfl_sync(0xffffffffu, rs, 0);
    re = __shfl_sync(0xffffffffu, re, 0);
    dv = __shfl_sync(0xffffffffu, dv, 0);

    if (LAYER == 1) {
        // lane covers cols [lane*4, lane*4+4)
        uint2 sr = ((const uint2*)(HT + (size_t)w * NCOL))[lane];
        float2 s0 = __half22float2(*(__half2*)&sr.x);
        float2 s1 = __half22float2(*(__half2*)&sr.y);
        // self term: ht1[w] * dinv[w]
        float4 a0 = make_float4(s0.x * dv, s0.y * dv, s1.x * dv, s1.y * dv);
        float4 a1 = make_float4(0.f, 0.f, 0.f, 0.f);
        for (int base = rs; base < re; base += 32) {
            int cnt = min(32, re - base);
            int idx = 0; float dvs = 0.f;
            if (lane < cnt) {
                idx = __ldg(g_csr + base + lane);
                dvs = __ldg(g_dinv + idx);
            }
            int k = 0;
            for (; k + 2 <= cnt; k += 2) {
                int n0 = __shfl_sync(0xffffffffu, idx, k);
                int n1 = __shfl_sync(0xffffffffu, idx, k + 1);
                float f0 = __shfl_sync(0xffffffffu, dvs, k);
                float f1 = __shfl_sync(0xffffffffu, dvs, k + 1);
                uint2 r0 = ((const uint2*)(HT + (size_t)n0 * NCOL))[lane];
                uint2 r1 = ((const uint2*)(HT + (size_t)n1 * NCOL))[lane];
                float2 p0 = __half22float2(*(__half2*)&r0.x);
                float2 p1 = __half22float2(*(__half2*)&r0.y);
                float2 q0 = __half22float2(*(__half2*)&r1.x);
                float2 q1 = __half22float2(*(__half2*)&r1.y);
                a0.x = fmaf(p0.x, f0, a0.x); a0.y = fmaf(p0.y, f0, a0.y);
                a0.z = fmaf(p1.x, f0, a0.z); a0.w = fmaf(p1.y, f0, a0.w);
                a1.x = fmaf(q0.x, f1, a1.x); a1.y = fmaf(q0.y, f1, a1.y);
                a1.z = fmaf(q1.x, f1, a1.z); a1.w = fmaf(q1.y, f1, a1.w);
            }
            if (k < cnt) {
                int n0 = __shfl_sync(0xffffffffu, idx, k);
                float f0 = __shfl_sync(0xffffffffu, dvs, k);
                uint2 r0 = ((const uint2*)(HT + (size_t)n0 * NCOL))[lane];
                float2 p0 = __half22float2(*(__half2*)&r0.x);
                float2 p1 = __half22float2(*(__half2*)&r0.y);
                a0.x = fmaf(p0.x, f0, a0.x); a0.y = fmaf(p0.y, f0, a0.y);
                a0.z = fmaf(p1.x, f0, a0.z); a0.w = fmaf(p1.y, f0, a0.w);
            }
        }
        float4 bb = ((const float4*)bias)[lane];
        float rx = fmaxf((a0.x + a1.x) * dv + bb.x, 0.f);
        float ry = fmaxf((a0.y + a1.y) * dv + bb.y, 0.f);
        float rz = fmaxf((a0.z + a1.z) * dv + bb.z, 0.f);
        float rw = fmaxf((a0.w + a1.w) * dv + bb.w, 0.f);
        uint2 st;
        *(__half2*)&st.x = __floats2half2_rn(rx, ry);
        *(__half2*)&st.y = __floats2half2_rn(rz, rw);
        ((uint2*)(g_agg1 + (size_t)w * NCOL))[lane] = st;
    } else {
        const __half2* self = (const __half2*)(HT + (size_t)w * NCOL);
        float2 a0 = __half22float2(self[lane]);
        float2 a1 = make_float2(0.f, 0.f);
        for (int base = rs; base < re; base += 32) {
            int cnt = min(32, re - base);
            int idx = (lane < cnt) ? __ldg(g_csr + base + lane) : 0;
            int k = 0;
            for (; k + 2 <= cnt; k += 2) {
                int n0 = __shfl_sync(0xffffffffu, idx, k);
                int n1 = __shfl_sync(0xffffffffu, idx, k + 1);
                float2 p = __half22float2(((const __half2*)(HT + (size_t)n0 * NCOL))[lane]);
                float2 q = __half22float2(((const __half2*)(HT + (size_t)n1 * NCOL))[lane]);
                a0.x += p.x; a0.y += p.y;
                a1.x += q.x; a1.y += q.y;
            }
            if (k < cnt) {
                int n0 = __shfl_sync(0xffffffffu, idx, k);
                float2 p = __half22float2(((const __half2*)(HT + (size_t)n0 * NCOL))[lane]);
                a0.x += p.x; a0.y += p.y;
            }
        }
        float2 bb = ((const float2*)bias)[lane];
        float2 r = make_float2(fmaxf((a0.x + a1.x) * dv + bb.x, 0.f),
                               fmaxf((a0.y + a1.y) * dv + bb.y, 0.f));
        ((float2*)(out_param + (size_t)w * NCOL))[lane] = r;
    }
}

// ---------------------------------------------------------------------------
extern "C" void kernel_launch(void* const* d_in, const int* in_sizes, int n_in,
                              void* d_out, int out_size)
{
    const float* x  = (const float*)d_in[0];
    const int*   ei = (const int*)  d_in[1];
    const float* W1 = (const float*)d_in[2];
    const float* b1 = (const float*)d_in[3];
    const float* W2 = (const float*)d_in[4];
    const float* b2 = (const float*)d_in[5];
    float* out = (float*)d_out;

    const int n  = in_sizes[0] / DIN;    // 50000
    const int ne = in_sizes[1] / 2;      // 800000
    const int* src = ei;
    const int* dst = ei + ne;

    const int nb_n  = (n + 255) / 256;
    const int nb_e4 = (ne / 4 + 255) / 256;
    const int nb_g  = (n + 127) / 128;
    const int nb_w  = (n + 7) / 8;

    // Fork: CSR build on side stream, gemm1 (independent of graph) on main.
    cudaStream_t s2;
    cudaStreamCreate(&s2);
    cudaEvent_t e1, e2;
    cudaEventCreateWithFlags(&e1, cudaEventDisableTiming);
    cudaEventCreateWithFlags(&e2, cudaEventDisableTiming);

    cudaEventRecord(e1, 0);
    cudaStreamWaitEvent(s2, e1, 0);

    // side stream: CSR + dinv
    k_zero <<<nb_n, 256, 0, s2>>>(n);
    k_count<<<nb_e4, 256, 0, s2>>>(dst, ne);
    k_alloc<<<nb_n, 256, 0, s2>>>(n);
    k_fill <<<nb_e4, 256, 0, s2>>>(src, dst, ne);
    cudaEventRecord(e2, s2);

    // main stream: gemm1 concurrent with CSR build
    k_gemm<1><<<nb_g, 256>>>(x, W1, n);          // g_ht1 = fp16(x@W1), unscaled

    // join
    cudaStreamWaitEvent(0, e2, 0);

    k_gather<1><<<nb_w, 256>>>(nullptr, b1, n);  // g_agg1 = fp16(relu(.+b1))
    k_gemm<2><<<nb_g, 256>>>(nullptr, W2, n);    // g_ht2 = fp16((agg1@W2)*dinv)
    k_gather<2><<<nb_w, 256>>>(out, b2, n);      // out (fp32)

    cudaEventDestroy(e1);
    cudaEventDestroy(e2);
    cudaStreamDestroy(s2);
}